// round 6
// baseline (speedup 1.0000x reference)
#include <cuda_runtime.h>
#include <cuda_bf16.h>
#include <math.h>

// ---------------------------------------------------------------------------
// Scratch (ping-pong).
// ---------------------------------------------------------------------------
__device__ float g_A[64 * 64 * 64 * 64];   // 67.1 MB
__device__ float g_B[64 * 128 * 32 * 32];  // 33.6 MB

// ---------------------------------------------------------------------------
// tf32 helpers
// ---------------------------------------------------------------------------
__device__ __forceinline__ unsigned cvt_tf32(float f) {
    unsigned u;
    asm("cvt.rna.tf32.f32 %0, %1;" : "=r"(u) : "f"(f));
    return u;
}
// split x into (hi, lo) tf32 pair stored as fp32 bit patterns
__device__ __forceinline__ float2 split_tf32(float x) {
    unsigned h = cvt_tf32(x);
    float hf = __uint_as_float(h);
    unsigned l = cvt_tf32(x - hf);
    float2 r; r.x = hf; r.y = __uint_as_float(l);
    return r;
}
__device__ __forceinline__ void mma_tf32(float* d,
                                         unsigned a0, unsigned a1, unsigned a2, unsigned a3,
                                         unsigned b0, unsigned b1) {
    asm volatile(
        "mma.sync.aligned.m16n8k8.row.col.f32.tf32.tf32.f32 "
        "{%0,%1,%2,%3}, {%4,%5,%6,%7}, {%8,%9}, {%0,%1,%2,%3};"
        : "+f"(d[0]), "+f"(d[1]), "+f"(d[2]), "+f"(d[3])
        : "r"(a0), "r"(a1), "r"(a2), "r"(a3), "r"(b0), "r"(b1));
}

// ---------------------------------------------------------------------------
// Implicit-GEMM conv3x3 SAME + bias + ReLU via 3xTF32 mma.sync.
// in [B,CI,H,W], wt [CO,CI,3,3], out [B,CO,H,W] (no pool here).
// Block: 256 thr = 8 warps (2 M x 4 N). CO tile = 64 (2 m16 tiles/warp).
// N tile = NB*NROW*W pixels. K = CI*9, staged ICT=8 channels at a time.
// smem holds (hi,lo) float2 pairs; im2col via address math at LDS.64 time.
// ---------------------------------------------------------------------------
template <int H, int W, int CI, int CO, int NB, int NROW>
__global__ void __launch_bounds__(256, 2)
conv_mma(const float* __restrict__ in, const float* __restrict__ wt,
         const float* __restrict__ bias, float* __restrict__ out)
{
    constexpr int ICT = 8;
    constexpr int SP2 = W + 2;                 // smem row stride (float2 units)
    constexpr int RS  = (NROW + 2) * SP2;      // per-channel slice stride
    constexpr int ST2 = 68;                    // weights row stride (64 co + pad)
    constexpr int BN  = NB * NROW * W;         // pixels per block
    constexpr int WN  = BN / 4;                // pixels per warp (4 N-warps)
    constexpr int NC  = WN / 8;                // n8-chunks per warp

    extern __shared__ float2 smem[];
    float2* s_in = smem;                        // NB*ICT*RS
    float2* s_w  = smem + NB * ICT * RS;        // 72*ST2

    const int tid  = threadIdx.x;
    const int warp = tid >> 5, lane = tid & 31;
    const int wm = warp & 1;        // 0..1  (32 co each)
    const int wn = warp >> 1;       // 0..3
    const int kk = lane & 3;        // k within 4
    const int ng = lane >> 2;       // n within 8 / co within 8

    const int ty0 = blockIdx.x * NROW;
    const int oc0 = blockIdx.y * 64;
    const int b0  = blockIdx.z * NB;

    // per-chunk B-fragment base offsets (float2 units)
    int boff[NC];
#pragma unroll
    for (int ch = 0; ch < NC; ch++) {
        int n = wn * WN + ch * 8 + ng;
        int x = n % W; int t = n / W;
        int yy = t % NROW; int img = t / NROW;
        boff[ch] = (img * ICT + kk) * RS + yy * SP2 + x;
    }
    const int aoff = kk * 9 * ST2 + wm * 32 + ng;

    float acc[2][NC][4];
#pragma unroll
    for (int mt = 0; mt < 2; mt++)
#pragma unroll
        for (int ch = 0; ch < NC; ch++)
#pragma unroll
            for (int j = 0; j < 4; j++) acc[mt][ch][j] = 0.f;

    for (int ic0 = 0; ic0 < CI; ic0 += ICT) {
        __syncthreads();
        // stage input slice (haloed, split hi/lo)
        constexpr int INEL = NB * ICT * (NROW + 2) * SP2;
        for (int i = tid; i < INEL; i += 256) {
            int ix = i % SP2; int t = i / SP2;
            int iy = t % (NROW + 2); t /= (NROW + 2);
            int ic = t % ICT; int im = t / ICT;
            int gy = ty0 + iy - 1, gx = ix - 1;
            float v = 0.f;
            if (gy >= 0 && gy < H && gx >= 0 && gx < W)
                v = in[(((size_t)(b0 + im) * CI + ic0 + ic) * H + gy) * W + gx];
            s_in[i] = split_tf32(v);
        }
        // stage weights slice: layout [(ic*9+kj)*ST2 + co]
        for (int i = tid; i < ICT * 9 * 64; i += 256) {
            int o = i / 72, r = i % 72;
            int ic = r / 9, kj = r % 9;
            float v = wt[((size_t)(oc0 + o) * CI + ic0 + ic) * 9 + kj];
            s_w[(ic * 9 + kj) * ST2 + o] = split_tf32(v);
        }
        __syncthreads();

#pragma unroll 1
        for (int kj = 0; kj < 9; kj++) {
            const int kyx = (kj / 3) * SP2 + (kj % 3);
            const float2* wp = s_w + kj * ST2 + aoff;
            float2 a[2][4];
#pragma unroll
            for (int mt = 0; mt < 2; mt++) {
                a[mt][0] = wp[mt * 16];
                a[mt][1] = wp[mt * 16 + 8];
                a[mt][2] = wp[4 * 9 * ST2 + mt * 16];
                a[mt][3] = wp[4 * 9 * ST2 + mt * 16 + 8];
            }
#pragma unroll
            for (int ch = 0; ch < NC; ch++) {
                float2 bv0 = s_in[boff[ch] + kyx];
                float2 bv1 = s_in[boff[ch] + kyx + 4 * RS];
                unsigned bh0 = __float_as_uint(bv0.x), bh1 = __float_as_uint(bv1.x);
                unsigned bl0 = __float_as_uint(bv0.y), bl1 = __float_as_uint(bv1.y);
#pragma unroll
                for (int mt = 0; mt < 2; mt++) {
                    unsigned ah0 = __float_as_uint(a[mt][0].x);
                    unsigned ah1 = __float_as_uint(a[mt][1].x);
                    unsigned ah2 = __float_as_uint(a[mt][2].x);
                    unsigned ah3 = __float_as_uint(a[mt][3].x);
                    // hi*hi
                    mma_tf32(acc[mt][ch], ah0, ah1, ah2, ah3, bh0, bh1);
                    // hi*lo
                    mma_tf32(acc[mt][ch], ah0, ah1, ah2, ah3, bl0, bl1);
                    // lo*hi
                    mma_tf32(acc[mt][ch],
                             __float_as_uint(a[mt][0].y), __float_as_uint(a[mt][1].y),
                             __float_as_uint(a[mt][2].y), __float_as_uint(a[mt][3].y),
                             bh0, bh1);
                }
            }
        }
    }

    // epilogue: bias + relu, scatter per mma C layout
#pragma unroll
    for (int mt = 0; mt < 2; mt++) {
        const int co = oc0 + wm * 32 + mt * 16 + ng;
        const float bv0 = bias[co];
        const float bv1 = bias[co + 8];
#pragma unroll
        for (int ch = 0; ch < NC; ch++) {
#pragma unroll
            for (int j = 0; j < 2; j++) {
                int n = wn * WN + ch * 8 + kk * 2 + j;
                int x = n % W; int t = n / W;
                int yy = t % NROW; int img = t / NROW;
                size_t o0 = (((size_t)(b0 + img) * CO + co) * H + ty0 + yy) * W + x;
                out[o0] = fmaxf(acc[mt][ch][j] + bv0, 0.f);
                out[o0 + (size_t)8 * H * W] = fmaxf(acc[mt][ch][j + 2] + bv1, 0.f);
            }
        }
    }
}

// ---------------------------------------------------------------------------
// Direct conv3x3 (kept for conv0, CI=3) + fused pool.
// ---------------------------------------------------------------------------
__device__ __forceinline__ void ldrow4(float* r, const float* p) {
    float4 u = *(const float4*)p;
    float4 v = *(const float4*)(p + 4);
    r[0] = u.x; r[1] = u.y; r[2] = u.z; r[3] = u.w;
    r[4] = v.x; r[5] = v.y; r[6] = v.z; r[7] = v.w;
}

template <int H, int W, int CI, int CO,
          int TPH, int TPW, int RPH, int RPW,
          int OCT, int RC, int ICT, bool POOL>
__global__ void __launch_bounds__((TPH / RPH) * (TPW / RPW) * (OCT / RC))
conv3x3_v2(const float* __restrict__ in, const float* __restrict__ wt,
           const float* __restrict__ bias, float* __restrict__ out)
{
    constexpr int NPXW = TPW / RPW;
    constexpr int NPX  = (TPH / RPH) * NPXW;
    constexpr int NCH  = OCT / RC;
    constexpr int NT   = NPX * NCH;
    constexpr int SP   = TPW + 4;

    __shared__ __align__(16) float s_in[ICT * (TPH + 2) * SP];
    __shared__ __align__(16) float s_w[ICT * OCT * 12];

    const int tiles_w = W / TPW;
    const int ty0 = (blockIdx.x / tiles_w) * TPH;
    const int tx0 = (blockIdx.x % tiles_w) * TPW;
    const int oc0 = blockIdx.y * OCT;
    const int b   = blockIdx.z;

    const int tid = threadIdx.x;
    const int pix = tid % NPX;
    const int ch  = tid / NPX;
    const int ly  = (pix / NPXW) * RPH;
    const int lx  = (pix % NPXW) * RPW;
    const int oc  = oc0 + ch * RC;

    float acc[RC][RPH][RPW];
#pragma unroll
    for (int c = 0; c < RC; c++)
#pragma unroll
        for (int yy = 0; yy < RPH; yy++)
#pragma unroll
            for (int xx = 0; xx < RPW; xx++) acc[c][yy][xx] = 0.f;

    for (int ic0 = 0; ic0 < CI; ic0 += ICT) {
        __syncthreads();
        constexpr int INEL = ICT * (TPH + 2) * (TPW + 2);
        for (int idx = tid; idx < INEL; idx += NT) {
            int t = idx;
            const int ix = t % (TPW + 2); t /= (TPW + 2);
            const int iy = t % (TPH + 2); t /= (TPH + 2);
            const int ic = t;
            const int gy = ty0 + iy - 1, gx = tx0 + ix - 1;
            float v = 0.f;
            if (gy >= 0 && gy < H && gx >= 0 && gx < W)
                v = in[(((size_t)b * CI + ic0 + ic) * H + gy) * W + gx];
            s_in[(ic * (TPH + 2) + iy) * SP + ix] = v;
        }
        for (int idx = tid; idx < ICT * OCT * 9; idx += NT) {
            int t = idx;
            const int tt = t % 9;   t /= 9;
            const int ic = t % ICT; t /= ICT;
            const int o  = t;
            s_w[(ic * OCT + o) * 12 + tt] =
                wt[((size_t)(oc0 + o) * CI + ic0 + ic) * 9 + tt];
        }
        __syncthreads();

#pragma unroll 1
        for (int ic = 0; ic < ICT; ic++) {
            const float* sbase = &s_in[(ic * (TPH + 2)) * SP];
            float wv[RC][9];
#pragma unroll
            for (int c = 0; c < RC; c++) {
                const float4* wp = (const float4*)&s_w[(ic * OCT + ch * RC + c) * 12];
                float4 w0 = wp[0], w1 = wp[1], w2 = wp[2];
                wv[c][0] = w0.x; wv[c][1] = w0.y; wv[c][2] = w0.z;
                wv[c][3] = w0.w; wv[c][4] = w1.x; wv[c][5] = w1.y;
                wv[c][6] = w1.z; wv[c][7] = w1.w; wv[c][8] = w2.x;
            }
            float r[3][8];
            ldrow4(r[0], sbase + (ly + 0) * SP + lx);
            ldrow4(r[1], sbase + (ly + 1) * SP + lx);
#pragma unroll
            for (int yy = 0; yy < RPH; yy++) {
                ldrow4(r[(yy + 2) % 3], sbase + (ly + yy + 2) * SP + lx);
                const int i0 = yy % 3, i1 = (yy + 1) % 3, i2 = (yy + 2) % 3;
#pragma unroll
                for (int c = 0; c < RC; c++)
#pragma unroll
                    for (int xx = 0; xx < RPW; xx++) {
                        float a = acc[c][yy][xx];
                        a = fmaf(wv[c][0], r[i0][xx],     a);
                        a = fmaf(wv[c][1], r[i0][xx + 1], a);
                        a = fmaf(wv[c][2], r[i0][xx + 2], a);
                        a = fmaf(wv[c][3], r[i1][xx],     a);
                        a = fmaf(wv[c][4], r[i1][xx + 1], a);
                        a = fmaf(wv[c][5], r[i1][xx + 2], a);
                        a = fmaf(wv[c][6], r[i2][xx],     a);
                        a = fmaf(wv[c][7], r[i2][xx + 1], a);
                        a = fmaf(wv[c][8], r[i2][xx + 2], a);
                        acc[c][yy][xx] = a;
                    }
            }
        }
    }

#pragma unroll
    for (int c = 0; c < RC; c++) {
        const float bv = bias[oc + c];
        if constexpr (POOL) {
            constexpr int H2 = H / 2, W2 = W / 2;
#pragma unroll
            for (int yy2 = 0; yy2 < RPH / 2; yy2++)
#pragma unroll
                for (int xx2 = 0; xx2 < RPW / 2; xx2++) {
                    float m = fmaxf(fmaxf(acc[c][2 * yy2][2 * xx2],
                                          acc[c][2 * yy2][2 * xx2 + 1]),
                                    fmaxf(acc[c][2 * yy2 + 1][2 * xx2],
                                          acc[c][2 * yy2 + 1][2 * xx2 + 1]));
                    out[(((size_t)b * CO + oc + c) * H2 + (ty0 + ly) / 2 + yy2) * W2
                        + (tx0 + lx) / 2 + xx2] = fmaxf(m + bv, 0.f);
                }
        } else {
#pragma unroll
            for (int yy = 0; yy < RPH; yy++)
#pragma unroll
                for (int xx = 0; xx < RPW; xx++)
                    out[(((size_t)b * CO + oc + c) * H + ty0 + ly + yy) * W
                        + tx0 + lx + xx] = fmaxf(acc[c][yy][xx] + bv, 0.f);
        }
    }
}

// ---------------------------------------------------------------------------
// 2x2 max pool, stride 2.
// ---------------------------------------------------------------------------
__global__ void maxpool2k(const float* __restrict__ in, float* __restrict__ out,
                          int total, int C, int H, int W)
{
    int i = blockIdx.x * blockDim.x + threadIdx.x;
    if (i >= total) return;
    int WO = W >> 1, HO = H >> 1;
    int x = i % WO;
    int t = i / WO;
    int y = t % HO; t /= HO;
    int c = t % C;
    int b = t / C;
    const float* p = in + ((size_t)(b * C + c) * H + 2 * y) * W + 2 * x;
    out[i] = fmaxf(fmaxf(p[0], p[1]), fmaxf(p[W], p[W + 1]));
}

// ---------------------------------------------------------------------------
// Engram mask + final 2x2 pool (4x4 -> 2x2) + flatten to [B, 2048].
// ---------------------------------------------------------------------------
__global__ void mask_pool_flatten(const float* __restrict__ h,
                                  const int* __restrict__ y,
                                  const int* __restrict__ b_table,
                                  float* __restrict__ out)
{
    int b = blockIdx.x;
    __shared__ int ids[128];
    int t = threadIdx.x;
    if (t < 128) ids[t] = b_table[y[b] * 128 + t];
    __syncthreads();
    int c = t;
    bool on = false;
#pragma unroll 16
    for (int j = 0; j < 128; j++) on |= (ids[j] == c);
    float m = on ? 1.f : 0.f;
    const float* p = h + ((size_t)(b * 512 + c) * 16);
#pragma unroll
    for (int py = 0; py < 2; py++)
#pragma unroll
        for (int px = 0; px < 2; px++) {
            const float* q = p + (2 * py) * 4 + 2 * px;
            float v = fmaxf(fmaxf(q[0], q[1]), fmaxf(q[4], q[5]));
            out[(size_t)b * 2048 + c * 4 + py * 2 + px] = v * m;
        }
}

// ---------------------------------------------------------------------------
// FC layers (fp32).
// ---------------------------------------------------------------------------
template <bool RELU>
__global__ void __launch_bounds__(256)
fc_v2(const float* __restrict__ A, const float* __restrict__ W,
      const float* __restrict__ bias, float* __restrict__ C,
      int N, int K, int Klen)
{
    __shared__ __align__(16) float sA[16 * 68];
    __shared__ __align__(16) float sB[16 * 34];
    const int n0 = blockIdx.x * 32;
    const int k0base = blockIdx.y * Klen;
    float* Cp = C + (size_t)blockIdx.y * 64 * N;
    const int tid = threadIdx.x;
    const int tm = (tid / 16) * 4;
    const int tn = (tid % 16) * 2;
    float acc[4][2] = {};

    for (int k0 = k0base; k0 < k0base + Klen; k0 += 16) {
        __syncthreads();
        for (int i = tid; i < 64 * 16; i += 256) {
            int r = i / 16, kk = i % 16;
            sA[kk * 68 + r] = A[(size_t)r * K + k0 + kk];
        }
        for (int i = tid; i < 32 * 16; i += 256) {
            int cidx = i / 16, kk = i % 16;
            int col = n0 + cidx;
            sB[kk * 34 + cidx] = (col < N) ? W[(size_t)col * K + k0 + kk] : 0.f;
        }
        __syncthreads();
#pragma unroll
        for (int kk = 0; kk < 16; kk++) {
            float4 a = *(const float4*)&sA[kk * 68 + tm];
            float2 b = *(const float2*)&sB[kk * 34 + tn];
            acc[0][0] = fmaf(a.x, b.x, acc[0][0]);
            acc[0][1] = fmaf(a.x, b.y, acc[0][1]);
            acc[1][0] = fmaf(a.y, b.x, acc[1][0]);
            acc[1][1] = fmaf(a.y, b.y, acc[1][1]);
            acc[2][0] = fmaf(a.z, b.x, acc[2][0]);
            acc[2][1] = fmaf(a.z, b.y, acc[2][1]);
            acc[3][0] = fmaf(a.w, b.x, acc[3][0]);
            acc[3][1] = fmaf(a.w, b.y, acc[3][1]);
        }
    }
#pragma unroll
    for (int j = 0; j < 2; j++) {
        int col = n0 + tn + j;
        if (col >= N) continue;
        float bv = bias ? bias[col] : 0.f;
#pragma unroll
        for (int i = 0; i < 4; i++) {
            float v = acc[i][j] + bv;
            if (RELU) v = fmaxf(v, 0.f);
            Cp[(size_t)(tm + i) * N + col] = v;
        }
    }
}

__global__ void fc3_combine(const float* __restrict__ part,
                            const float* __restrict__ bias,
                            float* __restrict__ out, int N, int total)
{
    int i = blockIdx.x * blockDim.x + threadIdx.x;
    if (i >= total) return;
    int n = i % N;
    out[i] = part[i] + part[64 * N + i] + part[2 * 64 * N + i]
           + part[3 * 64 * N + i] + bias[n];
}

// ---------------------------------------------------------------------------
// Launch
// ---------------------------------------------------------------------------
extern "C" void kernel_launch(void* const* d_in, const int* in_sizes, int n_in,
                              void* d_out, int out_size)
{
    const float* x    = (const float*)d_in[0];
    const int*   y    = (const int*)d_in[1];
    const int*   bt   = (const int*)d_in[2];
    const float* cw0  = (const float*)d_in[3];
    const float* cb0  = (const float*)d_in[4];
    const float* cw1  = (const float*)d_in[5];
    const float* cb1  = (const float*)d_in[6];
    const float* cw2a = (const float*)d_in[7];
    const float* cb2a = (const float*)d_in[8];
    const float* cw2b = (const float*)d_in[9];
    const float* cb2b = (const float*)d_in[10];
    const float* cw3a = (const float*)d_in[11];
    const float* cb3a = (const float*)d_in[12];
    const float* cw3b = (const float*)d_in[13];
    const float* cb3b = (const float*)d_in[14];
    const float* cw4a = (const float*)d_in[15];
    const float* cb4a = (const float*)d_in[16];
    const float* cw4b = (const float*)d_in[17];
    const float* cb4b = (const float*)d_in[18];
    const float* fw1  = (const float*)d_in[19];
    const float* fb1  = (const float*)d_in[20];
    const float* fw2  = (const float*)d_in[21];
    const float* fb2  = (const float*)d_in[22];
    const float* fw3  = (const float*)d_in[23];
    const float* fb3  = (const float*)d_in[24];

    float* A;
    float* Bp;
    cudaGetSymbolAddress((void**)&A, g_A);
    cudaGetSymbolAddress((void**)&Bp, g_B);

    // conv0 3->64 @64x64 + fused pool -> A [64,64,32,32]  (direct fp32)
    conv3x3_v2<64, 64, 3, 64, 16, 16, 4, 4, 64, 4, 3, true>
        <<<dim3(16, 1, 64), 256>>>(x, cw0, cb0, A);

    // conv1 64->128 @32x32 (mma) -> Bp unpooled, then pool -> A [64,128,16,16]
    {
        auto k = conv_mma<32, 32, 64, 128, 1, 8>;
        size_t sm = (size_t)(1 * 8 * 10 * 34 + 72 * 68) * 8;
        cudaFuncSetAttribute(k, cudaFuncAttributeMaxDynamicSharedMemorySize, (int)sm);
        k<<<dim3(4, 2, 64), 256, sm>>>(A, cw1, cb1, Bp);
        int total = 64 * 128 * 16 * 16;
        maxpool2k<<<(total + 255) / 256, 256>>>(Bp, A, total, 128, 32, 32);
    }
    // conv2a 128->256 @16x16 (mma) -> Bp
    {
        auto k = conv_mma<16, 16, 128, 256, 1, 16>;
        size_t sm = (size_t)(1 * 8 * 18 * 18 + 72 * 68) * 8;
        cudaFuncSetAttribute(k, cudaFuncAttributeMaxDynamicSharedMemorySize, (int)sm);
        k<<<dim3(1, 4, 64), 256, sm>>>(A, cw2a, cb2a, Bp);
    }
    // conv2b 256->256 @16x16 (mma) -> A unpooled, pool -> Bp [64,256,8,8]
    {
        auto k = conv_mma<16, 16, 256, 256, 1, 16>;
        size_t sm = (size_t)(1 * 8 * 18 * 18 + 72 * 68) * 8;
        cudaFuncSetAttribute(k, cudaFuncAttributeMaxDynamicSharedMemorySize, (int)sm);
        k<<<dim3(1, 4, 64), 256, sm>>>(Bp, cw2b, cb2b, A);
        int total = 64 * 256 * 8 * 8;
        maxpool2k<<<(total + 255) / 256, 256>>>(A, Bp, total, 256, 16, 16);
    }
    // conv3a 256->512 @8x8 (mma, 2 imgs/block) -> A
    {
        auto k = conv_mma<8, 8, 256, 512, 2, 8>;
        size_t sm = (size_t)(2 * 8 * 10 * 10 + 72 * 68) * 8;
        cudaFuncSetAttribute(k, cudaFuncAttributeMaxDynamicSharedMemorySize, (int)sm);
        k<<<dim3(1, 8, 32), 256, sm>>>(Bp, cw3a, cb3a, A);
    }
    // conv3b 512->512 @8x8 (mma) -> Bp unpooled, pool -> A [64,512,4,4]
    {
        auto k = conv_mma<8, 8, 512, 512, 2, 8>;
        size_t sm = (size_t)(2 * 8 * 10 * 10 + 72 * 68) * 8;
        cudaFuncSetAttribute(k, cudaFuncAttributeMaxDynamicSharedMemorySize, (int)sm);
        k<<<dim3(1, 8, 32), 256, sm>>>(A, cw3b, cb3b, Bp);
        int total = 64 * 512 * 4 * 4;
        maxpool2k<<<(total + 255) / 256, 256>>>(Bp, A, total, 512, 8, 8);
    }
    // conv4a 512->512 @4x4 (mma, 4 imgs/block) -> Bp
    {
        auto k = conv_mma<4, 4, 512, 512, 4, 4>;
        size_t sm = (size_t)(4 * 8 * 6 * 6 + 72 * 68) * 8;
        cudaFuncSetAttribute(k, cudaFuncAttributeMaxDynamicSharedMemorySize, (int)sm);
        k<<<dim3(1, 8, 16), 256, sm>>>(A, cw4a, cb4a, Bp);
    }
    // conv4b 512->512 @4x4 (mma) -> A
    {
        auto k = conv_mma<4, 4, 512, 512, 4, 4>;
        size_t sm = (size_t)(4 * 8 * 6 * 6 + 72 * 68) * 8;
        cudaFuncSetAttribute(k, cudaFuncAttributeMaxDynamicSharedMemorySize, (int)sm);
        k<<<dim3(1, 8, 16), 256, sm>>>(Bp, cw4b, cb4b, A);
    }

    // engram mask + pool -> flatten [64, 2048] -> Bp
    mask_pool_flatten<<<64, 512>>>(A, y, bt, Bp);

    // classifier
    fc_v2<true><<<dim3(128, 1), 256>>>(Bp, fw1, fb1, A, 4096, 2048, 2048);
    fc_v2<true><<<dim3(128, 1), 256>>>(A, fw2, fb2, Bp, 4096, 4096, 4096);
    fc_v2<false><<<dim3(32, 4), 256>>>(Bp, fw3, nullptr, A, 1000, 4096, 1024);
    fc3_combine<<<(64000 + 255) / 256, 256>>>(A, fb3, (float*)d_out, 1000, 64000);
}

// round 8
// speedup vs baseline: 1.1122x; 1.1122x over previous
#include <cuda_runtime.h>
#include <cuda_bf16.h>
#include <stdint.h>
#include <math.h>

// ---------------------------------------------------------------------------
// Scratch buffers. __device__ globals are zero-initialized at module load;
// halo rings of the padded split tensors are NEVER written -> stay zero.
// ---------------------------------------------------------------------------
__device__ float g_A[64 * 64 * 64 * 64];   // 67.1 MB generic fp32 scratch
__device__ float g_B[64 * 128 * 32 * 32];  // 33.6 MB generic fp32 scratch

// split activations (hi,lo) float2, padded [B,C,H+2,W+2]
__device__ float2 gS1[64 * 64  * 34 * 34];  // conv1 in  (37.9MB)
__device__ float2 gS2[64 * 128 * 18 * 18];  // conv2a in (21.2MB)
__device__ float2 gS3[64 * 256 * 18 * 18];  // conv2b in (42.5MB)
__device__ float2 gS4[64 * 256 * 10 * 10];  // conv3a in (13.1MB)
__device__ float2 gS5[64 * 512 * 10 * 10];  // conv3b in (26.2MB)
__device__ float2 gS6[64 * 512 * 6 * 6];    // conv4a in (9.4MB)
__device__ float2 gS7[64 * 512 * 6 * 6];    // conv4b in (9.4MB)

// split weights, layout [CO/32][CI*9][34] float2
__device__ float2 g_W[9792000];             // 78.3MB
// offsets (float2 units)
#define WOFF_C1  0
#define WOFF_C2A 78336
#define WOFF_C2B 391680
#define WOFF_C3A 1018368
#define WOFF_C3B 2271744
#define WOFF_C4A 4778496
#define WOFF_C4B 7285248

// ---------------------------------------------------------------------------
// tf32 helpers
// ---------------------------------------------------------------------------
__device__ __forceinline__ unsigned cvt_tf32(float f) {
    unsigned u;
    asm("cvt.rna.tf32.f32 %0, %1;" : "=r"(u) : "f"(f));
    return u;
}
__device__ __forceinline__ float2 split_tf32(float x) {
    unsigned h = cvt_tf32(x);
    float hf = __uint_as_float(h);
    unsigned l = cvt_tf32(x - hf);
    float2 r; r.x = hf; r.y = __uint_as_float(l);
    return r;
}
__device__ __forceinline__ void mma_tf32(float* d,
                                         unsigned a0, unsigned a1, unsigned a2, unsigned a3,
                                         unsigned b0, unsigned b1) {
    asm volatile(
        "mma.sync.aligned.m16n8k8.row.col.f32.tf32.tf32.f32 "
        "{%0,%1,%2,%3}, {%4,%5,%6,%7}, {%8,%9}, {%0,%1,%2,%3};"
        : "+f"(d[0]), "+f"(d[1]), "+f"(d[2]), "+f"(d[3])
        : "r"(a0), "r"(a1), "r"(a2), "r"(a3), "r"(b0), "r"(b1));
}
__device__ __forceinline__ void cp16(uint32_t dst, const void* src) {
    asm volatile("cp.async.cg.shared.global [%0], [%1], 16;" :: "r"(dst), "l"(src));
}

// ---------------------------------------------------------------------------
// Weight prep: [CO,CI,3,3] fp32 -> split float2 [CO/32][CI*9][34]
// ---------------------------------------------------------------------------
__global__ void prep_w(const float* __restrict__ wt, float2* __restrict__ out,
                       int CI, int total)
{
    int i = blockIdx.x * blockDim.x + threadIdx.x;
    if (i >= total) return;
    int co = i / (CI * 9);
    int r  = i % (CI * 9);          // ic*9+kj
    out[((size_t)(co >> 5) * CI * 9 + r) * 34 + (co & 31)] = split_tf32(wt[i]);
}

// ---------------------------------------------------------------------------
// Implicit-GEMM conv3x3 SAME + bias + ReLU via 3xTF32 mma.sync.
// Input: pre-split padded float2 [B,CI,H+2,W+2]. Weights: prepped split.
// Output: OUT_SPLIT ? split padded float2 [B,CO,H+2,W+2] : fp32 NCHW.
// 256 thr = 8 N-warps; CO tile = 32 (2 x m16 per warp).
// cp.async double-buffered staging of inputs and weights.
// ---------------------------------------------------------------------------
template <int H, int W, int CI, int CO, int NB, int NROW, bool OUT_SPLIT>
__global__ void __launch_bounds__(256, 2)
conv_mma3(const float2* __restrict__ in, const float2* __restrict__ wsp,
          const float* __restrict__ bias, void* __restrict__ outv)
{
    constexpr int ICT = 8, ST2 = 34;
    constexpr int WP = W + 2, HP = H + 2;
    constexpr int SP2 = W + 2;
    constexpr int RS  = (NROW + 2) * SP2;
    constexpr int BN  = NB * NROW * W;
    constexpr int WN  = BN / 8;
    constexpr int NC  = WN / 8;
    constexpr int SIN = NB * ICT * RS;        // f2 per input buffer
    constexpr int SWW = 72 * ST2;             // f2 per weight buffer
    constexpr int NCHI = (NROW + 2) * SP2 / 2;  // 16B chunks per (im,ic)
    constexpr int TCHI = NB * ICT * NCHI;
    constexpr int TCHW = SWW / 2;
    constexpr int NSLICE = CI / ICT;

    extern __shared__ float2 smem[];
    float2* sinb[2] = { smem, smem + SIN };
    float2* swb[2]  = { smem + 2 * SIN, smem + 2 * SIN + SWW };

    const int tid = threadIdx.x, warp = tid >> 5, lane = tid & 31;
    const int kk = lane & 3, ng = lane >> 2, wn = warp;
    const int ty0 = blockIdx.x * NROW;
    const int oc0 = blockIdx.y * 32;
    const int b0  = blockIdx.z * NB;

    int boff[NC];
#pragma unroll
    for (int ch = 0; ch < NC; ch++) {
        int n = wn * WN + ch * 8 + ng;
        int x = n % W; int t = n / W;
        int yy = t % NROW; int im = t / NROW;
        boff[ch] = (im * ICT + kk) * RS + yy * SP2 + x;
    }
    const int aoff = kk * 9 * ST2 + ng;

    float acc[2][NC][4];
#pragma unroll
    for (int mt = 0; mt < 2; mt++)
#pragma unroll
        for (int ch = 0; ch < NC; ch++)
#pragma unroll
            for (int j = 0; j < 4; j++) acc[mt][ch][j] = 0.f;

    auto stage = [&](int sl, int bufi) {
        const float2* ib = in + ((size_t)b0 * CI + sl * ICT) * (size_t)(HP * WP)
                         + (size_t)ty0 * WP;
        uint32_t sdi = (uint32_t)__cvta_generic_to_shared(sinb[bufi]);
        for (int i = tid; i < TCHI; i += 256) {
            int c = i % NCHI; int t = i / NCHI;
            int ic = t % ICT; int im = t / ICT;
            const float2* src = ib + ((size_t)im * CI + ic) * (HP * WP) + 2 * c;
            cp16(sdi + (uint32_t)(((im * ICT + ic) * RS + 2 * c) * 8), src);
        }
        const float2* wbp = wsp + ((size_t)blockIdx.y * CI + sl * ICT) * 9 * ST2;
        uint32_t sdw = (uint32_t)__cvta_generic_to_shared(swb[bufi]);
        for (int i = tid; i < TCHW; i += 256)
            cp16(sdw + (uint32_t)(i * 16), wbp + 2 * i);
        asm volatile("cp.async.commit_group;" ::: "memory");
    };

    stage(0, 0);
    for (int s = 0; s < NSLICE; s++) {
        if (s + 1 < NSLICE) {
            stage(s + 1, (s + 1) & 1);
            asm volatile("cp.async.wait_group 1;" ::: "memory");
        } else {
            asm volatile("cp.async.wait_group 0;" ::: "memory");
        }
        __syncthreads();

        const float2* si = sinb[s & 1];
        const float2* sw = swb[s & 1];
#pragma unroll 1
        for (int kj = 0; kj < 9; kj++) {
            const int kyx = (kj / 3) * SP2 + (kj % 3);
            const float2* wp = sw + kj * ST2 + aoff;
            float2 a[2][4];
#pragma unroll
            for (int mt = 0; mt < 2; mt++) {
                a[mt][0] = wp[mt * 16];
                a[mt][1] = wp[mt * 16 + 8];
                a[mt][2] = wp[4 * 9 * ST2 + mt * 16];
                a[mt][3] = wp[4 * 9 * ST2 + mt * 16 + 8];
            }
#pragma unroll
            for (int ch = 0; ch < NC; ch++) {
                float2 bv0 = si[boff[ch] + kyx];
                float2 bv1 = si[boff[ch] + kyx + 4 * RS];
                unsigned bh0 = __float_as_uint(bv0.x), bh1 = __float_as_uint(bv1.x);
                unsigned bl0 = __float_as_uint(bv0.y), bl1 = __float_as_uint(bv1.y);
#pragma unroll
                for (int mt = 0; mt < 2; mt++) {
                    unsigned ah0 = __float_as_uint(a[mt][0].x);
                    unsigned ah1 = __float_as_uint(a[mt][1].x);
                    unsigned ah2 = __float_as_uint(a[mt][2].x);
                    unsigned ah3 = __float_as_uint(a[mt][3].x);
                    mma_tf32(acc[mt][ch], ah0, ah1, ah2, ah3, bh0, bh1);
                    mma_tf32(acc[mt][ch], ah0, ah1, ah2, ah3, bl0, bl1);
                    mma_tf32(acc[mt][ch],
                             __float_as_uint(a[mt][0].y), __float_as_uint(a[mt][1].y),
                             __float_as_uint(a[mt][2].y), __float_as_uint(a[mt][3].y),
                             bh0, bh1);
                }
            }
        }
        __syncthreads();
    }

    // epilogue
#pragma unroll
    for (int mt = 0; mt < 2; mt++) {
        const int co = oc0 + mt * 16 + ng;
        const float bva = bias[co];
        const float bvb = bias[co + 8];
#pragma unroll
        for (int ch = 0; ch < NC; ch++) {
#pragma unroll
            for (int j = 0; j < 2; j++) {
                int n = wn * WN + ch * 8 + kk * 2 + j;
                int x = n % W; int t = n / W;
                int yy = t % NROW; int im = t / NROW;
                float v0 = fmaxf(acc[mt][ch][j] + bva, 0.f);
                float v1 = fmaxf(acc[mt][ch][j + 2] + bvb, 0.f);
                if constexpr (OUT_SPLIT) {
                    float2* o = (float2*)outv;
                    size_t base = (((size_t)(b0 + im) * CO + co) * (H + 2)
                                   + (ty0 + yy + 1)) * (W + 2) + (x + 1);
                    o[base] = split_tf32(v0);
                    o[base + (size_t)8 * (H + 2) * (W + 2)] = split_tf32(v1);
                } else {
                    float* o = (float*)outv;
                    size_t base = (((size_t)(b0 + im) * CO + co) * H + (ty0 + yy)) * W + x;
                    o[base] = v0;
                    o[base + (size_t)8 * H * W] = v1;
                }
            }
        }
    }
}

// ---------------------------------------------------------------------------
// conv0: direct fp32 3->64 @64x64, fused pool, writes SPLIT PADDED [64,64,34,34].
// ---------------------------------------------------------------------------
__global__ void __launch_bounds__(256)
conv0_k(const float* __restrict__ in, const float* __restrict__ wt,
        const float* __restrict__ bias, float2* __restrict__ out)
{
    constexpr int H = 64, W = 64, CI = 3, CO = 64;
    constexpr int TPH = 16, TPW = 16, RPH = 4, RPW = 4, OCT = 64, RC = 4;
    constexpr int NPXW = TPW / RPW;
    constexpr int NPX  = (TPH / RPH) * NPXW;   // 16
    constexpr int SP   = TPW + 4;

    __shared__ __align__(16) float s_in[CI * (TPH + 2) * SP];
    __shared__ __align__(16) float s_w[CI * OCT * 12];

    const int tiles_w = W / TPW;
    const int ty0 = (blockIdx.x / tiles_w) * TPH;
    const int tx0 = (blockIdx.x % tiles_w) * TPW;
    const int b   = blockIdx.z;

    const int tid = threadIdx.x;
    const int pix = tid % NPX;
    const int ch  = tid / NPX;
    const int ly  = (pix / NPXW) * RPH;
    const int lx  = (pix % NPXW) * RPW;
    const int oc  = ch * RC;

    float acc[RC][RPH][RPW];
#pragma unroll
    for (int c = 0; c < RC; c++)
#pragma unroll
        for (int yy = 0; yy < RPH; yy++)
#pragma unroll
            for (int xx = 0; xx < RPW; xx++) acc[c][yy][xx] = 0.f;

    {
        constexpr int INEL = CI * (TPH + 2) * (TPW + 2);
        for (int idx = tid; idx < INEL; idx += 256) {
            int t = idx;
            const int ix = t % (TPW + 2); t /= (TPW + 2);
            const int iy = t % (TPH + 2); t /= (TPH + 2);
            const int ic = t;
            const int gy = ty0 + iy - 1, gx = tx0 + ix - 1;
            float v = 0.f;
            if (gy >= 0 && gy < H && gx >= 0 && gx < W)
                v = in[(((size_t)b * CI + ic) * H + gy) * W + gx];
            s_in[(ic * (TPH + 2) + iy) * SP + ix] = v;
        }
        for (int idx = tid; idx < CI * OCT * 9; idx += 256) {
            int t = idx;
            const int tt = t % 9;  t /= 9;
            const int ic = t % CI; t /= CI;
            const int o  = t;
            s_w[(ic * OCT + o) * 12 + tt] = wt[((size_t)o * CI + ic) * 9 + tt];
        }
        __syncthreads();

#pragma unroll
        for (int ic = 0; ic < CI; ic++) {
            const float* sbase = &s_in[(ic * (TPH + 2)) * SP];
            float wv[RC][9];
#pragma unroll
            for (int c = 0; c < RC; c++) {
                const float4* wp = (const float4*)&s_w[(ic * OCT + ch * RC + c) * 12];
                float4 w0 = wp[0], w1 = wp[1], w2 = wp[2];
                wv[c][0] = w0.x; wv[c][1] = w0.y; wv[c][2] = w0.z;
                wv[c][3] = w0.w; wv[c][4] = w1.x; wv[c][5] = w1.y;
                wv[c][6] = w1.z; wv[c][7] = w1.w; wv[c][8] = w2.x;
            }
            float r[3][8];
            {
                float4 u = *(const float4*)(sbase + (ly + 0) * SP + lx);
                float4 v = *(const float4*)(sbase + (ly + 0) * SP + lx + 4);
                r[0][0]=u.x;r[0][1]=u.y;r[0][2]=u.z;r[0][3]=u.w;r[0][4]=v.x;r[0][5]=v.y;r[0][6]=v.z;r[0][7]=v.w;
                u = *(const float4*)(sbase + (ly + 1) * SP + lx);
                v = *(const float4*)(sbase + (ly + 1) * SP + lx + 4);
                r[1][0]=u.x;r[1][1]=u.y;r[1][2]=u.z;r[1][3]=u.w;r[1][4]=v.x;r[1][5]=v.y;r[1][6]=v.z;r[1][7]=v.w;
            }
#pragma unroll
            for (int yy = 0; yy < RPH; yy++) {
                {
                    int rr = (yy + 2) % 3;
                    float4 u = *(const float4*)(sbase + (ly + yy + 2) * SP + lx);
                    float4 v = *(const float4*)(sbase + (ly + yy + 2) * SP + lx + 4);
                    r[rr][0]=u.x;r[rr][1]=u.y;r[rr][2]=u.z;r[rr][3]=u.w;r[rr][4]=v.x;r[rr][5]=v.y;r[rr][6]=v.z;r[rr][7]=v.w;
                }
                const int i0 = yy % 3, i1 = (yy + 1) % 3, i2 = (yy + 2) % 3;
#pragma unroll
                for (int c = 0; c < RC; c++)
#pragma unroll
                    for (int xx = 0; xx < RPW; xx++) {
                        float a = acc[c][yy][xx];
                        a = fmaf(wv[c][0], r[i0][xx],     a);
                        a = fmaf(wv[c][1], r[i0][xx + 1], a);
                        a = fmaf(wv[c][2], r[i0][xx + 2], a);
                        a = fmaf(wv[c][3], r[i1][xx],     a);
                        a = fmaf(wv[c][4], r[i1][xx + 1], a);
                        a = fmaf(wv[c][5], r[i1][xx + 2], a);
                        a = fmaf(wv[c][6], r[i2][xx],     a);
                        a = fmaf(wv[c][7], r[i2][xx + 1], a);
                        a = fmaf(wv[c][8], r[i2][xx + 2], a);
                        acc[c][yy][xx] = a;
                    }
            }
        }
    }

    // pool 2x2 + bias + relu + split + padded store [64,64,34,34]
#pragma unroll
    for (int c = 0; c < RC; c++) {
        const float bv = bias[oc + c];
#pragma unroll
        for (int y2 = 0; y2 < RPH / 2; y2++)
#pragma unroll
            for (int x2 = 0; x2 < RPW / 2; x2++) {
                float m = fmaxf(fmaxf(acc[c][2*y2][2*x2], acc[c][2*y2][2*x2+1]),
                                fmaxf(acc[c][2*y2+1][2*x2], acc[c][2*y2+1][2*x2+1]));
                float v = fmaxf(m + bv, 0.f);
                int py = (ty0 + ly) / 2 + y2, px = (tx0 + lx) / 2 + x2;
                out[(((size_t)b * 64 + oc + c) * 34 + py + 1) * 34 + (px + 1)]
                    = split_tf32(v);
            }
    }
}

// ---------------------------------------------------------------------------
// 2x2 maxpool on fp32 NCHW -> split padded float2 [B,C,H/2+2,W/2+2]
// ---------------------------------------------------------------------------
__global__ void pool_split(const float* __restrict__ in, float2* __restrict__ out,
                           int total, int C, int H, int W)
{
    int i = blockIdx.x * blockDim.x + threadIdx.x;
    if (i >= total) return;
    int WO = W >> 1, HO = H >> 1;
    int x = i % WO;
    int t = i / WO;
    int y = t % HO; t /= HO;
    int c = t % C;
    int b = t / C;
    const float* p = in + ((size_t)(b * C + c) * H + 2 * y) * W + 2 * x;
    float v = fmaxf(fmaxf(p[0], p[1]), fmaxf(p[W], p[W + 1]));
    out[(((size_t)(b * C + c)) * (HO + 2) + y + 1) * (WO + 2) + x + 1] = split_tf32(v);
}

// ---------------------------------------------------------------------------
// Engram mask + final 2x2 pool (4x4 -> 2x2) + flatten to [B, 2048].
// ---------------------------------------------------------------------------
__global__ void mask_pool_flatten(const float* __restrict__ h,
                                  const int* __restrict__ y,
                                  const int* __restrict__ b_table,
                                  float* __restrict__ out)
{
    int b = blockIdx.x;
    __shared__ int ids[128];
    int t = threadIdx.x;
    if (t < 128) ids[t] = b_table[y[b] * 128 + t];
    __syncthreads();
    int c = t;
    bool on = false;
#pragma unroll 16
    for (int j = 0; j < 128; j++) on |= (ids[j] == c);
    float m = on ? 1.f : 0.f;
    const float* p = h + ((size_t)(b * 512 + c) * 16);
#pragma unroll
    for (int py = 0; py < 2; py++)
#pragma unroll
        for (int px = 0; px < 2; px++) {
            const float* q = p + (2 * py) * 4 + 2 * px;
            float v = fmaxf(fmaxf(q[0], q[1]), fmaxf(q[4], q[5]));
            out[(size_t)b * 2048 + c * 4 + py * 2 + px] = v * m;
        }
}

// ---------------------------------------------------------------------------
// FC layers (fp32).
// ---------------------------------------------------------------------------
template <bool RELU>
__global__ void __launch_bounds__(256)
fc_v2(const float* __restrict__ A, const float* __restrict__ W,
      const float* __restrict__ bias, float* __restrict__ C,
      int N, int K, int Klen)
{
    __shared__ __align__(16) float sA[16 * 68];
    __shared__ __align__(16) float sB[16 * 34];
    const int n0 = blockIdx.x * 32;
    const int k0base = blockIdx.y * Klen;
    float* Cp = C + (size_t)blockIdx.y * 64 * N;
    const int tid = threadIdx.x;
    const int tm = (tid / 16) * 4;
    const int tn = (tid % 16) * 2;
    float acc[4][2] = {};

    for (int k0 = k0base; k0 < k0base + Klen; k0 += 16) {
        __syncthreads();
        for (int i = tid; i < 64 * 16; i += 256) {
            int r = i / 16, kk = i % 16;
            sA[kk * 68 + r] = A[(size_t)r * K + k0 + kk];
        }
        for (int i = tid; i < 32 * 16; i += 256) {
            int cidx = i / 16, kk = i % 16;
            int col = n0 + cidx;
            sB[kk * 34 + cidx] = (col < N) ? W[(size_t)col * K + k0 + kk] : 0.f;
        }
        __syncthreads();
#pragma unroll
        for (int kk = 0; kk < 16; kk++) {
            float4 a = *(const float4*)&sA[kk * 68 + tm];
            float2 b = *(const float2*)&sB[kk * 34 + tn];
            acc[0][0] = fmaf(a.x, b.x, acc[0][0]);
            acc[0][1] = fmaf(a.x, b.y, acc[0][1]);
            acc[1][0] = fmaf(a.y, b.x, acc[1][0]);
            acc[1][1] = fmaf(a.y, b.y, acc[1][1]);
            acc[2][0] = fmaf(a.z, b.x, acc[2][0]);
            acc[2][1] = fmaf(a.z, b.y, acc[2][1]);
            acc[3][0] = fmaf(a.w, b.x, acc[3][0]);
            acc[3][1] = fmaf(a.w, b.y, acc[3][1]);
        }
    }
#pragma unroll
    for (int j = 0; j < 2; j++) {
        int col = n0 + tn + j;
        if (col >= N) continue;
        float bv = bias ? bias[col] : 0.f;
#pragma unroll
        for (int i = 0; i < 4; i++) {
            float v = acc[i][j] + bv;
            if (RELU) v = fmaxf(v, 0.f);
            Cp[(size_t)(tm + i) * N + col] = v;
        }
    }
}

__global__ void fc3_combine(const float* __restrict__ part,
                            const float* __restrict__ bias,
                            float* __restrict__ out, int N, int total)
{
    int i = blockIdx.x * blockDim.x + threadIdx.x;
    if (i >= total) return;
    int n = i % N;
    out[i] = part[i] + part[64 * N + i] + part[2 * 64 * N + i]
           + part[3 * 64 * N + i] + bias[n];
}

// ---------------------------------------------------------------------------
// Launch
// ---------------------------------------------------------------------------
extern "C" void kernel_launch(void* const* d_in, const int* in_sizes, int n_in,
                              void* d_out, int out_size)
{
    const float* x    = (const float*)d_in[0];
    const int*   y    = (const int*)d_in[1];
    const int*   bt   = (const int*)d_in[2];
    const float* cw0  = (const float*)d_in[3];
    const float* cb0  = (const float*)d_in[4];
    const float* cw1  = (const float*)d_in[5];
    const float* cb1  = (const float*)d_in[6];
    const float* cw2a = (const float*)d_in[7];
    const float* cb2a = (const float*)d_in[8];
    const float* cw2b = (const float*)d_in[9];
    const float* cb2b = (const float*)d_in[10];
    const float* cw3a = (const float*)d_in[11];
    const float* cb3a = (const float*)d_in[12];
    const float* cw3b = (const float*)d_in[13];
    const float* cb3b = (const float*)d_in[14];
    const float* cw4a = (const float*)d_in[15];
    const float* cb4a = (const float*)d_in[16];
    const float* cw4b = (const float*)d_in[17];
    const float* cb4b = (const float*)d_in[18];
    const float* fw1  = (const float*)d_in[19];
    const float* fb1  = (const float*)d_in[20];
    const float* fw2  = (const float*)d_in[21];
    const float* fb2  = (const float*)d_in[22];
    const float* fw3  = (const float*)d_in[23];
    const float* fb3  = (const float*)d_in[24];

    float* A;  float* Bp;
    float2 *S1, *S2, *S3, *S4, *S5, *S6, *S7, *Wsp;
    cudaGetSymbolAddress((void**)&A, g_A);
    cudaGetSymbolAddress((void**)&Bp, g_B);
    cudaGetSymbolAddress((void**)&S1, gS1);
    cudaGetSymbolAddress((void**)&S2, gS2);
    cudaGetSymbolAddress((void**)&S3, gS3);
    cudaGetSymbolAddress((void**)&S4, gS4);
    cudaGetSymbolAddress((void**)&S5, gS5);
    cudaGetSymbolAddress((void**)&S6, gS6);
    cudaGetSymbolAddress((void**)&S7, gS7);
    cudaGetSymbolAddress((void**)&Wsp, g_W);

    // weight prep (each replay; cheap)
    prep_w<<<(128*64*9 + 255)/256, 256>>>(cw1,  Wsp + WOFF_C1,  64,  128*64*9);
    prep_w<<<(256*128*9 + 255)/256, 256>>>(cw2a, Wsp + WOFF_C2A, 128, 256*128*9);
    prep_w<<<(256*256*9 + 255)/256, 256>>>(cw2b, Wsp + WOFF_C2B, 256, 256*256*9);
    prep_w<<<(512*256*9 + 255)/256, 256>>>(cw3a, Wsp + WOFF_C3A, 256, 512*256*9);
    prep_w<<<(512*512*9 + 255)/256, 256>>>(cw3b, Wsp + WOFF_C3B, 512, 512*512*9);
    prep_w<<<(512*512*9 + 255)/256, 256>>>(cw4a, Wsp + WOFF_C4A, 512, 512*512*9);
    prep_w<<<(512*512*9 + 255)/256, 256>>>(cw4b, Wsp + WOFF_C4B, 512, 512*512*9);

    // conv0 (direct) + pool -> S1 split padded [64,64,34,34]
    conv0_k<<<dim3(16, 1, 64), 256>>>(x, cw0, cb0, S1);

    // conv1 64->128 @32x32 -> Bp fp32; pool -> S2
    {
        auto k = conv_mma3<32, 32, 64, 128, 1, 8, false>;
        size_t sm = (size_t)(2 * (8 * 340) + 2 * (72 * 34)) * 8;
        cudaFuncSetAttribute(k, cudaFuncAttributeMaxDynamicSharedMemorySize, (int)sm);
        k<<<dim3(4, 4, 64), 256, sm>>>(S1, Wsp + WOFF_C1, cb1, Bp);
        int total = 64 * 128 * 16 * 16;
        pool_split<<<(total + 255)/256, 256>>>(Bp, S2, total, 128, 32, 32);
    }
    // conv2a 128->256 @16x16 -> S3 split
    {
        auto k = conv_mma3<16, 16, 128, 256, 1, 16, true>;
        size_t sm = (size_t)(2 * (8 * 324) + 2 * (72 * 34)) * 8;
        cudaFuncSetAttribute(k, cudaFuncAttributeMaxDynamicSharedMemorySize, (int)sm);
        k<<<dim3(1, 8, 64), 256, sm>>>(S2, Wsp + WOFF_C2A, cb2a, S3);
    }
    // conv2b 256->256 @16x16 -> Bp fp32; pool -> S4
    {
        auto k = conv_mma3<16, 16, 256, 256, 1, 16, false>;
        size_t sm = (size_t)(2 * (8 * 324) + 2 * (72 * 34)) * 8;
        cudaFuncSetAttribute(k, cudaFuncAttributeMaxDynamicSharedMemorySize, (int)sm);
        k<<<dim3(1, 8, 64), 256, sm>>>(S3, Wsp + WOFF_C2B, cb2b, Bp);
        int total = 64 * 256 * 8 * 8;
        pool_split<<<(total + 255)/256, 256>>>(Bp, S4, total, 256, 16, 16);
    }
    // conv3a 256->512 @8x8 (NB=2) -> S5 split
    {
        auto k = conv_mma3<8, 8, 256, 512, 2, 8, true>;
        size_t sm = (size_t)(2 * (16 * 100) + 2 * (72 * 34)) * 8;
        cudaFuncSetAttribute(k, cudaFuncAttributeMaxDynamicSharedMemorySize, (int)sm);
        k<<<dim3(1, 16, 32), 256, sm>>>(S4, Wsp + WOFF_C3A, cb3a, S5);
    }
    // conv3b 512->512 @8x8 -> Bp fp32; pool -> S6
    {
        auto k = conv_mma3<8, 8, 512, 512, 2, 8, false>;
        size_t sm = (size_t)(2 * (16 * 100) + 2 * (72 * 34)) * 8;
        cudaFuncSetAttribute(k, cudaFuncAttributeMaxDynamicSharedMemorySize, (int)sm);
        k<<<dim3(1, 16, 32), 256, sm>>>(S5, Wsp + WOFF_C3B, cb3b, Bp);
        int total = 64 * 512 * 4 * 4;
        pool_split<<<(total + 255)/256, 256>>>(Bp, S6, total, 512, 8, 8);
    }
    // conv4a 512->512 @4x4 (NB=8) -> S7 split
    {
        auto k = conv_mma3<4, 4, 512, 512, 8, 4, true>;
        size_t sm = (size_t)(2 * (64 * 36) + 2 * (72 * 34)) * 8;
        cudaFuncSetAttribute(k, cudaFuncAttributeMaxDynamicSharedMemorySize, (int)sm);
        k<<<dim3(1, 16, 8), 256, sm>>>(S6, Wsp + WOFF_C4A, cb4a, S7);
    }
    // conv4b 512->512 @4x4 -> Bp fp32
    {
        auto k = conv_mma3<4, 4, 512, 512, 8, 4, false>;
        size_t sm = (size_t)(2 * (64 * 36) + 2 * (72 * 34)) * 8;
        cudaFuncSetAttribute(k, cudaFuncAttributeMaxDynamicSharedMemorySize, (int)sm);
        k<<<dim3(1, 16, 8), 256, sm>>>(S7, Wsp + WOFF_C4B, cb4b, Bp);
    }

    // engram mask + pool -> flatten [64, 2048] -> A
    mask_pool_flatten<<<64, 512>>>(Bp, y, bt, A);

    // classifier
    fc_v2<true><<<dim3(128, 1), 256>>>(A, fw1, fb1, Bp, 4096, 2048, 2048);
    fc_v2<true><<<dim3(128, 1), 256>>>(Bp, fw2, fb2, A, 4096, 4096, 4096);
    fc_v2<false><<<dim3(32, 4), 256>>>(A, fw3, nullptr, Bp, 1000, 4096, 1024);
    fc3_combine<<<(64000 + 255)/256, 256>>>(Bp, fb3, (float*)d_out, 1000, 64000);
}

// round 9
// speedup vs baseline: 1.1548x; 1.0383x over previous
#include <cuda_runtime.h>
#include <cuda_bf16.h>
#include <stdint.h>
#include <math.h>

// ---------------------------------------------------------------------------
// Scratch buffers. __device__ globals are zero-initialized at module load;
// halo rings of the padded split tensors are NEVER written -> stay zero.
// ---------------------------------------------------------------------------
__device__ float g_A[64 * 64 * 64 * 64];   // 67.1 MB generic fp32 scratch
__device__ float g_B[64 * 128 * 32 * 32];  // 33.6 MB generic fp32 scratch

// split activations (hi,lo) float2, padded [B,C,H+2,W+2]
__device__ float2 gS1[64 * 64  * 34 * 34];  // conv1 in
__device__ float2 gS2[64 * 128 * 18 * 18];  // conv2a in
__device__ float2 gS3[64 * 256 * 18 * 18];  // conv2b in
__device__ float2 gS4[64 * 256 * 10 * 10];  // conv3a in
__device__ float2 gS5[64 * 512 * 10 * 10];  // conv3b in
__device__ float2 gS6[64 * 512 * 6 * 6];    // conv4a in
__device__ float2 gS7[64 * 512 * 6 * 6];    // conv4b in

// split weights, layout [CO/32][CI*9][36] float2  (ST2=36: conflict-free)
__device__ float2 g_W[10368000];            // 82.9MB
// offsets (float2 units)
#define WOFF_C1  0
#define WOFF_C2A 82944
#define WOFF_C2B 414720
#define WOFF_C3A 1078272
#define WOFF_C3B 2405376
#define WOFF_C4A 5059584
#define WOFF_C4B 7713792

// ---------------------------------------------------------------------------
// tf32 helpers
// ---------------------------------------------------------------------------
__device__ __forceinline__ unsigned cvt_tf32(float f) {
    unsigned u;
    asm("cvt.rna.tf32.f32 %0, %1;" : "=r"(u) : "f"(f));
    return u;
}
__device__ __forceinline__ float2 split_tf32(float x) {
    unsigned h = cvt_tf32(x);
    float hf = __uint_as_float(h);
    unsigned l = cvt_tf32(x - hf);
    float2 r; r.x = hf; r.y = __uint_as_float(l);
    return r;
}
__device__ __forceinline__ void mma_tf32(float* d,
                                         unsigned a0, unsigned a1, unsigned a2, unsigned a3,
                                         unsigned b0, unsigned b1) {
    asm volatile(
        "mma.sync.aligned.m16n8k8.row.col.f32.tf32.tf32.f32 "
        "{%0,%1,%2,%3}, {%4,%5,%6,%7}, {%8,%9}, {%0,%1,%2,%3};"
        : "+f"(d[0]), "+f"(d[1]), "+f"(d[2]), "+f"(d[3])
        : "r"(a0), "r"(a1), "r"(a2), "r"(a3), "r"(b0), "r"(b1));
}
__device__ __forceinline__ void cp16(uint32_t dst, const void* src) {
    asm volatile("cp.async.cg.shared.global [%0], [%1], 16;" :: "r"(dst), "l"(src));
}

// ---------------------------------------------------------------------------
// Weight prep (ONE launch): [CO,CI,3,3] fp32 -> split float2 [CO/32][CI*9][36]
// ---------------------------------------------------------------------------
__global__ void prep_w_all(const float* __restrict__ w1, const float* __restrict__ w2a,
                           const float* __restrict__ w2b, const float* __restrict__ w3a,
                           const float* __restrict__ w3b, const float* __restrict__ w4a,
                           const float* __restrict__ w4b, float2* __restrict__ out)
{
    int i = blockIdx.x * blockDim.x + threadIdx.x;
    const float* src; int CI; size_t woff; int base;
    if      (i < 73728)   { src = w1;  CI = 64;  woff = WOFF_C1;  base = 0; }
    else if (i < 368640)  { src = w2a; CI = 128; woff = WOFF_C2A; base = 73728; }
    else if (i < 958464)  { src = w2b; CI = 256; woff = WOFF_C2B; base = 368640; }
    else if (i < 2138112) { src = w3a; CI = 256; woff = WOFF_C3A; base = 958464; }
    else if (i < 4497408) { src = w3b; CI = 512; woff = WOFF_C3B; base = 2138112; }
    else if (i < 6856704) { src = w4a; CI = 512; woff = WOFF_C4A; base = 4497408; }
    else if (i < 9216000) { src = w4b; CI = 512; woff = WOFF_C4B; base = 6856704; }
    else return;
    int j  = i - base;
    int co = j / (CI * 9);
    int r  = j % (CI * 9);
    out[woff + ((size_t)(co >> 5) * CI * 9 + r) * 36 + (co & 31)] = split_tf32(src[j]);
}

// ---------------------------------------------------------------------------
// Implicit-GEMM conv3x3 SAME + bias + ReLU via 3xTF32 mma.sync.
// Input: pre-split padded float2 [B,CI,H+2,W+2]. Weights: prepped split.
// Output: OUT_SPLIT ? split padded float2 [B,CO,H+2,W+2] : fp32 NCHW.
// 256 thr = 8 N-warps; CO tile = 32 (2 x m16 per warp).
// cp.async double-buffered; 3-pass mma schedule breaks acc RAW chains.
// ---------------------------------------------------------------------------
template <int H, int W, int CI, int CO, int NB, int NROW, bool OUT_SPLIT>
__global__ void __launch_bounds__(256, 2)
conv_mma3(const float2* __restrict__ in, const float2* __restrict__ wsp,
          const float* __restrict__ bias, void* __restrict__ outv)
{
    constexpr int ICT = 8, ST2 = 36;
    constexpr int WP = W + 2, HP = H + 2;
    constexpr int SP2 = W + 2;
    constexpr int RS  = (NROW + 2) * SP2;
    constexpr int BN  = NB * NROW * W;
    constexpr int WN  = BN / 8;
    constexpr int NC  = WN / 8;
    constexpr int SIN = NB * ICT * RS;          // f2 per input buffer
    constexpr int SWW = 72 * ST2;               // f2 per weight buffer
    constexpr int NCHI = (NROW + 2) * SP2 / 2;  // 16B chunks per (im,ic)
    constexpr int TCHI = NB * ICT * NCHI;
    constexpr int TCHW = SWW / 2;
    constexpr int NSLICE = CI / ICT;

    extern __shared__ float2 smem[];
    float2* sinb[2] = { smem, smem + SIN };
    float2* swb[2]  = { smem + 2 * SIN, smem + 2 * SIN + SWW };

    const int tid = threadIdx.x, warp = tid >> 5, lane = tid & 31;
    const int kk = lane & 3, ng = lane >> 2, wn = warp;
    const int ty0 = blockIdx.x * NROW;
    const int oc0 = blockIdx.y * 32;
    const int b0  = blockIdx.z * NB;

    int boff[NC];
#pragma unroll
    for (int ch = 0; ch < NC; ch++) {
        int n = wn * WN + ch * 8 + ng;
        int x = n % W; int t = n / W;
        int yy = t % NROW; int im = t / NROW;
        boff[ch] = (im * ICT + kk) * RS + yy * SP2 + x;
    }
    const int aoff = kk * 9 * ST2 + ng;

    float acc[2][NC][4];
#pragma unroll
    for (int mt = 0; mt < 2; mt++)
#pragma unroll
        for (int ch = 0; ch < NC; ch++)
#pragma unroll
            for (int j = 0; j < 4; j++) acc[mt][ch][j] = 0.f;

    auto stage = [&](int sl, int bufi) {
        const float2* ib = in + ((size_t)b0 * CI + sl * ICT) * (size_t)(HP * WP)
                         + (size_t)ty0 * WP;
        uint32_t sdi = (uint32_t)__cvta_generic_to_shared(sinb[bufi]);
        for (int i = tid; i < TCHI; i += 256) {
            int c = i % NCHI; int t = i / NCHI;
            int ic = t % ICT; int im = t / ICT;
            const float2* src = ib + ((size_t)im * CI + ic) * (HP * WP) + 2 * c;
            cp16(sdi + (uint32_t)(((im * ICT + ic) * RS + 2 * c) * 8), src);
        }
        const float2* wbp = wsp + ((size_t)blockIdx.y * CI + sl * ICT) * 9 * ST2;
        uint32_t sdw = (uint32_t)__cvta_generic_to_shared(swb[bufi]);
        for (int i = tid; i < TCHW; i += 256)
            cp16(sdw + (uint32_t)(i * 16), wbp + 2 * i);
        asm volatile("cp.async.commit_group;" ::: "memory");
    };

    stage(0, 0);
    for (int s = 0; s < NSLICE; s++) {
        if (s + 1 < NSLICE) {
            stage(s + 1, (s + 1) & 1);
            asm volatile("cp.async.wait_group 1;" ::: "memory");
        } else {
            asm volatile("cp.async.wait_group 0;" ::: "memory");
        }
        __syncthreads();

        const float2* si = sinb[s & 1];
        const float2* sw = swb[s & 1];
#pragma unroll 1
        for (int kj = 0; kj < 9; kj++) {
            const int kyx = (kj / 3) * SP2 + (kj % 3);
            const float2* wp = sw + kj * ST2 + aoff;
            float2 a[2][4];
#pragma unroll
            for (int mt = 0; mt < 2; mt++) {
                a[mt][0] = wp[mt * 16];
                a[mt][1] = wp[mt * 16 + 8];
                a[mt][2] = wp[4 * 9 * ST2 + mt * 16];
                a[mt][3] = wp[4 * 9 * ST2 + mt * 16 + 8];
            }
            unsigned bh[NC][2], bl[NC][2];
#pragma unroll
            for (int ch = 0; ch < NC; ch++) {
                float2 bv0 = si[boff[ch] + kyx];
                float2 bv1 = si[boff[ch] + kyx + 4 * RS];
                bh[ch][0] = __float_as_uint(bv0.x);
                bh[ch][1] = __float_as_uint(bv1.x);
                bl[ch][0] = __float_as_uint(bv0.y);
                bl[ch][1] = __float_as_uint(bv1.y);
            }
            // pass 1: hi*hi  (independent accs back-to-back)
#pragma unroll
            for (int ch = 0; ch < NC; ch++)
#pragma unroll
                for (int mt = 0; mt < 2; mt++)
                    mma_tf32(acc[mt][ch],
                             __float_as_uint(a[mt][0].x), __float_as_uint(a[mt][1].x),
                             __float_as_uint(a[mt][2].x), __float_as_uint(a[mt][3].x),
                             bh[ch][0], bh[ch][1]);
            // pass 2: hi*lo
#pragma unroll
            for (int ch = 0; ch < NC; ch++)
#pragma unroll
                for (int mt = 0; mt < 2; mt++)
                    mma_tf32(acc[mt][ch],
                             __float_as_uint(a[mt][0].x), __float_as_uint(a[mt][1].x),
                             __float_as_uint(a[mt][2].x), __float_as_uint(a[mt][3].x),
                             bl[ch][0], bl[ch][1]);
            // pass 3: lo*hi
#pragma unroll
            for (int ch = 0; ch < NC; ch++)
#pragma unroll
                for (int mt = 0; mt < 2; mt++)
                    mma_tf32(acc[mt][ch],
                             __float_as_uint(a[mt][0].y), __float_as_uint(a[mt][1].y),
                             __float_as_uint(a[mt][2].y), __float_as_uint(a[mt][3].y),
                             bh[ch][0], bh[ch][1]);
        }
        __syncthreads();
    }

    // epilogue
#pragma unroll
    for (int mt = 0; mt < 2; mt++) {
        const int co = oc0 + mt * 16 + ng;
        const float bva = bias[co];
        const float bvb = bias[co + 8];
#pragma unroll
        for (int ch = 0; ch < NC; ch++) {
#pragma unroll
            for (int j = 0; j < 2; j++) {
                int n = wn * WN + ch * 8 + kk * 2 + j;
                int x = n % W; int t = n / W;
                int yy = t % NROW; int im = t / NROW;
                float v0 = fmaxf(acc[mt][ch][j] + bva, 0.f);
                float v1 = fmaxf(acc[mt][ch][j + 2] + bvb, 0.f);
                if constexpr (OUT_SPLIT) {
                    float2* o = (float2*)outv;
                    size_t base = (((size_t)(b0 + im) * CO + co) * (H + 2)
                                   + (ty0 + yy + 1)) * (W + 2) + (x + 1);
                    o[base] = split_tf32(v0);
                    o[base + (size_t)8 * (H + 2) * (W + 2)] = split_tf32(v1);
                } else {
                    float* o = (float*)outv;
                    size_t base = (((size_t)(b0 + im) * CO + co) * H + (ty0 + yy)) * W + x;
                    o[base] = v0;
                    o[base + (size_t)8 * H * W] = v1;
                }
            }
        }
    }
}

// ---------------------------------------------------------------------------
// conv0: direct fp32 3->64 @64x64, fused pool, writes SPLIT PADDED [64,64,34,34].
// ---------------------------------------------------------------------------
__global__ void __launch_bounds__(256)
conv0_k(const float* __restrict__ in, const float* __restrict__ wt,
        const float* __restrict__ bias, float2* __restrict__ out)
{
    constexpr int H = 64, W = 64, CI = 3, CO = 64;
    constexpr int TPH = 16, TPW = 16, RPH = 4, RPW = 4, OCT = 64, RC = 4;
    constexpr int NPXW = TPW / RPW;
    constexpr int NPX  = (TPH / RPH) * NPXW;   // 16
    constexpr int SP   = TPW + 4;

    __shared__ __align__(16) float s_in[CI * (TPH + 2) * SP];
    __shared__ __align__(16) float s_w[CI * OCT * 12];

    const int tiles_w = W / TPW;
    const int ty0 = (blockIdx.x / tiles_w) * TPH;
    const int tx0 = (blockIdx.x % tiles_w) * TPW;
    const int b   = blockIdx.z;

    const int tid = threadIdx.x;
    const int pix = tid % NPX;
    const int ch  = tid / NPX;
    const int ly  = (pix / NPXW) * RPH;
    const int lx  = (pix % NPXW) * RPW;
    const int oc  = ch * RC;

    float acc[RC][RPH][RPW];
#pragma unroll
    for (int c = 0; c < RC; c++)
#pragma unroll
        for (int yy = 0; yy < RPH; yy++)
#pragma unroll
            for (int xx = 0; xx < RPW; xx++) acc[c][yy][xx] = 0.f;

    {
        constexpr int INEL = CI * (TPH + 2) * (TPW + 2);
        for (int idx = tid; idx < INEL; idx += 256) {
            int t = idx;
            const int ix = t % (TPW + 2); t /= (TPW + 2);
            const int iy = t % (TPH + 2); t /= (TPH + 2);
            const int ic = t;
            const int gy = ty0 + iy - 1, gx = tx0 + ix - 1;
            float v = 0.f;
            if (gy >= 0 && gy < H && gx >= 0 && gx < W)
                v = in[(((size_t)b * CI + ic) * H + gy) * W + gx];
            s_in[(ic * (TPH + 2) + iy) * SP + ix] = v;
        }
        for (int idx = tid; idx < CI * OCT * 9; idx += 256) {
            int t = idx;
            const int tt = t % 9;  t /= 9;
            const int ic = t % CI; t /= CI;
            const int o  = t;
            s_w[(ic * OCT + o) * 12 + tt] = wt[((size_t)o * CI + ic) * 9 + tt];
        }
        __syncthreads();

#pragma unroll
        for (int ic = 0; ic < CI; ic++) {
            const float* sbase = &s_in[(ic * (TPH + 2)) * SP];
            float wv[RC][9];
#pragma unroll
            for (int c = 0; c < RC; c++) {
                const float4* wp = (const float4*)&s_w[(ic * OCT + ch * RC + c) * 12];
                float4 w0 = wp[0], w1 = wp[1], w2 = wp[2];
                wv[c][0] = w0.x; wv[c][1] = w0.y; wv[c][2] = w0.z;
                wv[c][3] = w0.w; wv[c][4] = w1.x; wv[c][5] = w1.y;
                wv[c][6] = w1.z; wv[c][7] = w1.w; wv[c][8] = w2.x;
            }
            float r[3][8];
            {
                float4 u = *(const float4*)(sbase + (ly + 0) * SP + lx);
                float4 v = *(const float4*)(sbase + (ly + 0) * SP + lx + 4);
                r[0][0]=u.x;r[0][1]=u.y;r[0][2]=u.z;r[0][3]=u.w;r[0][4]=v.x;r[0][5]=v.y;r[0][6]=v.z;r[0][7]=v.w;
                u = *(const float4*)(sbase + (ly + 1) * SP + lx);
                v = *(const float4*)(sbase + (ly + 1) * SP + lx + 4);
                r[1][0]=u.x;r[1][1]=u.y;r[1][2]=u.z;r[1][3]=u.w;r[1][4]=v.x;r[1][5]=v.y;r[1][6]=v.z;r[1][7]=v.w;
            }
#pragma unroll
            for (int yy = 0; yy < RPH; yy++) {
                {
                    int rr = (yy + 2) % 3;
                    float4 u = *(const float4*)(sbase + (ly + yy + 2) * SP + lx);
                    float4 v = *(const float4*)(sbase + (ly + yy + 2) * SP + lx + 4);
                    r[rr][0]=u.x;r[rr][1]=u.y;r[rr][2]=u.z;r[rr][3]=u.w;r[rr][4]=v.x;r[rr][5]=v.y;r[rr][6]=v.z;r[rr][7]=v.w;
                }
                const int i0 = yy % 3, i1 = (yy + 1) % 3, i2 = (yy + 2) % 3;
#pragma unroll
                for (int c = 0; c < RC; c++)
#pragma unroll
                    for (int xx = 0; xx < RPW; xx++) {
                        float a = acc[c][yy][xx];
                        a = fmaf(wv[c][0], r[i0][xx],     a);
                        a = fmaf(wv[c][1], r[i0][xx + 1], a);
                        a = fmaf(wv[c][2], r[i0][xx + 2], a);
                        a = fmaf(wv[c][3], r[i1][xx],     a);
                        a = fmaf(wv[c][4], r[i1][xx + 1], a);
                        a = fmaf(wv[c][5], r[i1][xx + 2], a);
                        a = fmaf(wv[c][6], r[i2][xx],     a);
                        a = fmaf(wv[c][7], r[i2][xx + 1], a);
                        a = fmaf(wv[c][8], r[i2][xx + 2], a);
                        acc[c][yy][xx] = a;
                    }
            }
        }
    }

#pragma unroll
    for (int c = 0; c < RC; c++) {
        const float bv = bias[oc + c];
#pragma unroll
        for (int y2 = 0; y2 < RPH / 2; y2++)
#pragma unroll
            for (int x2 = 0; x2 < RPW / 2; x2++) {
                float m = fmaxf(fmaxf(acc[c][2*y2][2*x2], acc[c][2*y2][2*x2+1]),
                                fmaxf(acc[c][2*y2+1][2*x2], acc[c][2*y2+1][2*x2+1]));
                float v = fmaxf(m + bv, 0.f);
                int py = (ty0 + ly) / 2 + y2, px = (tx0 + lx) / 2 + x2;
                out[(((size_t)b * 64 + oc + c) * 34 + py + 1) * 34 + (px + 1)]
                    = split_tf32(v);
            }
    }
}

// ---------------------------------------------------------------------------
// 2x2 maxpool on fp32 NCHW -> split padded float2 [B,C,H/2+2,W/2+2]
// ---------------------------------------------------------------------------
__global__ void pool_split(const float* __restrict__ in, float2* __restrict__ out,
                           int total, int C, int H, int W)
{
    int i = blockIdx.x * blockDim.x + threadIdx.x;
    if (i >= total) return;
    int WO = W >> 1, HO = H >> 1;
    int x = i % WO;
    int t = i / WO;
    int y = t % HO; t /= HO;
    int c = t % C;
    int b = t / C;
    const float* p = in + ((size_t)(b * C + c) * H + 2 * y) * W + 2 * x;
    float v = fmaxf(fmaxf(p[0], p[1]), fmaxf(p[W], p[W + 1]));
    out[(((size_t)(b * C + c)) * (HO + 2) + y + 1) * (WO + 2) + x + 1] = split_tf32(v);
}

// ---------------------------------------------------------------------------
// Engram mask + final 2x2 pool (4x4 -> 2x2) + flatten to [B, 2048].
// ---------------------------------------------------------------------------
__global__ void mask_pool_flatten(const float* __restrict__ h,
                                  const int* __restrict__ y,
                                  const int* __restrict__ b_table,
                                  float* __restrict__ out)
{
    int b = blockIdx.x;
    __shared__ int ids[128];
    int t = threadIdx.x;
    if (t < 128) ids[t] = b_table[y[b] * 128 + t];
    __syncthreads();
    int c = t;
    bool on = false;
#pragma unroll 16
    for (int j = 0; j < 128; j++) on |= (ids[j] == c);
    float m = on ? 1.f : 0.f;
    const float* p = h + ((size_t)(b * 512 + c) * 16);
#pragma unroll
    for (int py = 0; py < 2; py++)
#pragma unroll
        for (int px = 0; px < 2; px++) {
            const float* q = p + (2 * py) * 4 + 2 * px;
            float v = fmaxf(fmaxf(q[0], q[1]), fmaxf(q[4], q[5]));
            out[(size_t)b * 2048 + c * 4 + py * 2 + px] = v * m;
        }
}

// ---------------------------------------------------------------------------
// FC layers (fp32).
// ---------------------------------------------------------------------------
template <bool RELU>
__global__ void __launch_bounds__(256)
fc_v2(const float* __restrict__ A, const float* __restrict__ W,
      const float* __restrict__ bias, float* __restrict__ C,
      int N, int K, int Klen)
{
    __shared__ __align__(16) float sA[16 * 68];
    __shared__ __align__(16) float sB[16 * 34];
    const int n0 = blockIdx.x * 32;
    const int k0base = blockIdx.y * Klen;
    float* Cp = C + (size_t)blockIdx.y * 64 * N;
    const int tid = threadIdx.x;
    const int tm = (tid / 16) * 4;
    const int tn = (tid % 16) * 2;
    float acc[4][2] = {};

    for (int k0 = k0base; k0 < k0base + Klen; k0 += 16) {
        __syncthreads();
        for (int i = tid; i < 64 * 16; i += 256) {
            int r = i / 16, kk = i % 16;
            sA[kk * 68 + r] = A[(size_t)r * K + k0 + kk];
        }
        for (int i = tid; i < 32 * 16; i += 256) {
            int cidx = i / 16, kk = i % 16;
            int col = n0 + cidx;
            sB[kk * 34 + cidx] = (col < N) ? W[(size_t)col * K + k0 + kk] : 0.f;
        }
        __syncthreads();
#pragma unroll
        for (int kk = 0; kk < 16; kk++) {
            float4 a = *(const float4*)&sA[kk * 68 + tm];
            float2 b = *(const float2*)&sB[kk * 34 + tn];
            acc[0][0] = fmaf(a.x, b.x, acc[0][0]);
            acc[0][1] = fmaf(a.x, b.y, acc[0][1]);
            acc[1][0] = fmaf(a.y, b.x, acc[1][0]);
            acc[1][1] = fmaf(a.y, b.y, acc[1][1]);
            acc[2][0] = fmaf(a.z, b.x, acc[2][0]);
            acc[2][1] = fmaf(a.z, b.y, acc[2][1]);
            acc[3][0] = fmaf(a.w, b.x, acc[3][0]);
            acc[3][1] = fmaf(a.w, b.y, acc[3][1]);
        }
    }
#pragma unroll
    for (int j = 0; j < 2; j++) {
        int col = n0 + tn + j;
        if (col >= N) continue;
        float bv = bias ? bias[col] : 0.f;
#pragma unroll
        for (int i = 0; i < 4; i++) {
            float v = acc[i][j] + bv;
            if (RELU) v = fmaxf(v, 0.f);
            Cp[(size_t)(tm + i) * N + col] = v;
        }
    }
}

__global__ void fc3_combine(const float* __restrict__ part,
                            const float* __restrict__ bias,
                            float* __restrict__ out, int N, int total)
{
    int i = blockIdx.x * blockDim.x + threadIdx.x;
    if (i >= total) return;
    int n = i % N;
    out[i] = part[i] + part[64 * N + i] + part[2 * 64 * N + i]
           + part[3 * 64 * N + i] + bias[n];
}

// ---------------------------------------------------------------------------
// Launch
// ---------------------------------------------------------------------------
extern "C" void kernel_launch(void* const* d_in, const int* in_sizes, int n_in,
                              void* d_out, int out_size)
{
    const float* x    = (const float*)d_in[0];
    const int*   y    = (const int*)d_in[1];
    const int*   bt   = (const int*)d_in[2];
    const float* cw0  = (const float*)d_in[3];
    const float* cb0  = (const float*)d_in[4];
    const float* cw1  = (const float*)d_in[5];
    const float* cb1  = (const float*)d_in[6];
    const float* cw2a = (const float*)d_in[7];
    const float* cb2a = (const float*)d_in[8];
    const float* cw2b = (const float*)d_in[9];
    const float* cb2b = (const float*)d_in[10];
    const float* cw3a = (const float*)d_in[11];
    const float* cb3a = (const float*)d_in[12];
    const float* cw3b = (const float*)d_in[13];
    const float* cb3b = (const float*)d_in[14];
    const float* cw4a = (const float*)d_in[15];
    const float* cb4a = (const float*)d_in[16];
    const float* cw4b = (const float*)d_in[17];
    const float* cb4b = (const float*)d_in[18];
    const float* fw1  = (const float*)d_in[19];
    const float* fb1  = (const float*)d_in[20];
    const float* fw2  = (const float*)d_in[21];
    const float* fb2  = (const float*)d_in[22];
    const float* fw3  = (const float*)d_in[23];
    const float* fb3  = (const float*)d_in[24];

    float* A;  float* Bp;
    float2 *S1, *S2, *S3, *S4, *S5, *S6, *S7, *Wsp;
    cudaGetSymbolAddress((void**)&A, g_A);
    cudaGetSymbolAddress((void**)&Bp, g_B);
    cudaGetSymbolAddress((void**)&S1, gS1);
    cudaGetSymbolAddress((void**)&S2, gS2);
    cudaGetSymbolAddress((void**)&S3, gS3);
    cudaGetSymbolAddress((void**)&S4, gS4);
    cudaGetSymbolAddress((void**)&S5, gS5);
    cudaGetSymbolAddress((void**)&S6, gS6);
    cudaGetSymbolAddress((void**)&S7, gS7);
    cudaGetSymbolAddress((void**)&Wsp, g_W);

    // 1: weight prep (single launch)
    prep_w_all<<<(9216000 + 255) / 256, 256>>>(cw1, cw2a, cw2b, cw3a, cw3b,
                                               cw4a, cw4b, Wsp);
    // 2: conv0 (direct) + pool -> S1 split padded
    conv0_k<<<dim3(16, 1, 64), 256>>>(x, cw0, cb0, S1);

    // 3: conv1 64->128 @32x32 -> Bp fp32; 4: pool -> S2
    {
        auto k = conv_mma3<32, 32, 64, 128, 1, 8, false>;
        size_t sm = (size_t)(2 * (8 * 340) + 2 * (72 * 36)) * 8;
        cudaFuncSetAttribute(k, cudaFuncAttributeMaxDynamicSharedMemorySize, (int)sm);
        k<<<dim3(4, 4, 64), 256, sm>>>(S1, Wsp + WOFF_C1, cb1, Bp);
        int total = 64 * 128 * 16 * 16;
        pool_split<<<(total + 255)/256, 256>>>(Bp, S2, total, 128, 32, 32);
    }
    // 5: conv2a 128->256 @16x16 -> S3 split
    {
        auto k = conv_mma3<16, 16, 128, 256, 1, 16, true>;
        size_t sm = (size_t)(2 * (8 * 324) + 2 * (72 * 36)) * 8;
        cudaFuncSetAttribute(k, cudaFuncAttributeMaxDynamicSharedMemorySize, (int)sm);
        k<<<dim3(1, 8, 64), 256, sm>>>(S2, Wsp + WOFF_C2A, cb2a, S3);
    }
    // 6: conv2b 256->256 @16x16 -> Bp fp32  (ncu -s 5 profiles THIS); pool -> S4
    {
        auto k = conv_mma3<16, 16, 256, 256, 1, 16, false>;
        size_t sm = (size_t)(2 * (8 * 324) + 2 * (72 * 36)) * 8;
        cudaFuncSetAttribute(k, cudaFuncAttributeMaxDynamicSharedMemorySize, (int)sm);
        k<<<dim3(1, 8, 64), 256, sm>>>(S3, Wsp + WOFF_C2B, cb2b, Bp);
        int total = 64 * 256 * 8 * 8;
        pool_split<<<(total + 255)/256, 256>>>(Bp, S4, total, 256, 16, 16);
    }
    // conv3a 256->512 @8x8 (NB=2) -> S5 split
    {
        auto k = conv_mma3<8, 8, 256, 512, 2, 8, true>;
        size_t sm = (size_t)(2 * (16 * 100) + 2 * (72 * 36)) * 8;
        cudaFuncSetAttribute(k, cudaFuncAttributeMaxDynamicSharedMemorySize, (int)sm);
        k<<<dim3(1, 16, 32), 256, sm>>>(S4, Wsp + WOFF_C3A, cb3a, S5);
    }
    // conv3b 512->512 @8x8 -> Bp fp32; pool -> S6
    {
        auto k = conv_mma3<8, 8, 512, 512, 2, 8, false>;
        size_t sm = (size_t)(2 * (16 * 100) + 2 * (72 * 36)) * 8;
        cudaFuncSetAttribute(k, cudaFuncAttributeMaxDynamicSharedMemorySize, (int)sm);
        k<<<dim3(1, 16, 32), 256, sm>>>(S5, Wsp + WOFF_C3B, cb3b, Bp);
        int total = 64 * 512 * 4 * 4;
        pool_split<<<(total + 255)/256, 256>>>(Bp, S6, total, 512, 8, 8);
    }
    // conv4a 512->512 @4x4 (NB=8) -> S7 split
    {
        auto k = conv_mma3<4, 4, 512, 512, 8, 4, true>;
        size_t sm = (size_t)(2 * (64 * 36) + 2 * (72 * 36)) * 8;
        cudaFuncSetAttribute(k, cudaFuncAttributeMaxDynamicSharedMemorySize, (int)sm);
        k<<<dim3(1, 16, 8), 256, sm>>>(S6, Wsp + WOFF_C4A, cb4a, S7);
    }
    // conv4b 512->512 @4x4 -> Bp fp32
    {
        auto k = conv_mma3<4, 4, 512, 512, 8, 4, false>;
        size_t sm = (size_t)(2 * (64 * 36) + 2 * (72 * 36)) * 8;
        cudaFuncSetAttribute(k, cudaFuncAttributeMaxDynamicSharedMemorySize, (int)sm);
        k<<<dim3(1, 16, 8), 256, sm>>>(S7, Wsp + WOFF_C4B, cb4b, Bp);
    }

    // engram mask + pool -> flatten [64, 2048] -> A
    mask_pool_flatten<<<64, 512>>>(Bp, y, bt, A);

    // classifier
    fc_v2<true><<<dim3(128, 1), 256>>>(A, fw1, fb1, Bp, 4096, 2048, 2048);
    fc_v2<true><<<dim3(128, 1), 256>>>(Bp, fw2, fb2, A, 4096, 4096, 4096);
    fc_v2<false><<<dim3(32, 4), 256>>>(A, fw3, nullptr, Bp, 1000, 4096, 1024);
    fc3_combine<<<(64000 + 255)/256, 256>>>(Bp, fb3, (float*)d_out, 1000, 64000);
}

// round 11
// speedup vs baseline: 1.7140x; 1.4842x over previous
#include <cuda_runtime.h>
#include <cuda_bf16.h>
#include <stdint.h>
#include <math.h>

// ---------------------------------------------------------------------------
// Scratch. __device__ globals zero-init; halo rings never written -> stay 0.
// Activations: bf16 channel-pair packed, h (hi) and m (residual) arrays,
// layout [B][C/2][(H+2)*(W+2)] uint32 (lo16 = even channel).
// ---------------------------------------------------------------------------
__device__ float g_A[64 * 64 * 64 * 64];   // fp32 scratch
__device__ float g_B[64 * 128 * 32 * 32];  // fp32 scratch

__device__ uint32_t gS1h[64 * 32  * 34 * 34], gS1m[64 * 32  * 34 * 34];
__device__ uint32_t gS2h[64 * 64  * 18 * 18], gS2m[64 * 64  * 18 * 18];
__device__ uint32_t gS3h[64 * 128 * 18 * 18], gS3m[64 * 128 * 18 * 18];
__device__ uint32_t gS4h[64 * 128 * 10 * 10], gS4m[64 * 128 * 10 * 10];
__device__ uint32_t gS5h[64 * 256 * 10 * 10], gS5m[64 * 256 * 10 * 10];
__device__ uint32_t gS6h[64 * 256 * 6 * 6],   gS6m[64 * 256 * 6 * 6];
__device__ uint32_t gS7h[64 * 256 * 6 * 6],   gS7m[64 * 256 * 6 * 6];

// Weights: rows [(CO/32 group)][(CI/2)*9][40] uint32 packed pairs; h + m arrays.
__device__ uint32_t g_WH[5760000], g_WM[5760000];   // 144000 rows * 40
// row offsets per layer
#define ROFF_C1  0
#define ROFF_C2A 1152
#define ROFF_C2B 5760
#define ROFF_C3A 14976
#define ROFF_C3B 33408
#define ROFF_C4A 70272
#define ROFF_C4B 107136

// ---------------------------------------------------------------------------
// helpers
// ---------------------------------------------------------------------------
__device__ __forceinline__ uint32_t packbf2(float lo, float hi) {
    uint32_t r;
    asm("cvt.rn.bf16x2.f32 %0, %1, %2;" : "=r"(r) : "f"(hi), "f"(lo));
    return r;
}
__device__ __forceinline__ void mma_bf16(float* d,
                                         uint32_t a0, uint32_t a1, uint32_t a2, uint32_t a3,
                                         uint32_t b0, uint32_t b1) {
    asm volatile(
        "mma.sync.aligned.m16n8k16.row.col.f32.bf16.bf16.f32 "
        "{%0,%1,%2,%3}, {%4,%5,%6,%7}, {%8,%9}, {%0,%1,%2,%3};"
        : "+f"(d[0]), "+f"(d[1]), "+f"(d[2]), "+f"(d[3])
        : "r"(a0), "r"(a1), "r"(a2), "r"(a3), "r"(b0), "r"(b1));
}
__device__ __forceinline__ void cp16(uint32_t dst, const void* src) {
    asm volatile("cp.async.cg.shared.global [%0], [%1], 16;" :: "r"(dst), "l"(src));
}

// ---------------------------------------------------------------------------
// Weight prep (one launch): fp32 OIHW -> packed bf16 pair h/m rows (stride 40)
// ---------------------------------------------------------------------------
__global__ void prep_w_all(const float* __restrict__ w1, const float* __restrict__ w2a,
                           const float* __restrict__ w2b, const float* __restrict__ w3a,
                           const float* __restrict__ w3b, const float* __restrict__ w4a,
                           const float* __restrict__ w4b)
{
    int i = blockIdx.x * blockDim.x + threadIdx.x;
    const float* src; int CI; int roff; int base;
    if      (i < 36864)   { src = w1;  CI = 64;  roff = ROFF_C1;  base = 0; }
    else if (i < 184320)  { src = w2a; CI = 128; roff = ROFF_C2A; base = 36864; }
    else if (i < 479232)  { src = w2b; CI = 256; roff = ROFF_C2B; base = 184320; }
    else if (i < 1069056) { src = w3a; CI = 256; roff = ROFF_C3A; base = 479232; }
    else if (i < 2248704) { src = w3b; CI = 512; roff = ROFF_C3B; base = 1069056; }
    else if (i < 3428352) { src = w4a; CI = 512; roff = ROFF_C4A; base = 2248704; }
    else if (i < 4608000) { src = w4b; CI = 512; roff = ROFF_C4B; base = 3428352; }
    else return;
    int j  = i - base;
    int seg = (CI / 2) * 9;
    int co = j / seg;
    int r  = j % seg;            // pc*9 + kj
    int pc = r / 9, kj = r % 9;
    float v0 = src[((size_t)co * CI + 2 * pc) * 9 + kj];
    float v1 = src[((size_t)co * CI + 2 * pc + 1) * 9 + kj];
    float h0 = __bfloat162float(__float2bfloat16(v0));
    float h1 = __bfloat162float(__float2bfloat16(v1));
    size_t row = (size_t)roff + (size_t)(co >> 5) * seg + r;
    g_WH[row * 40 + (co & 31)] = packbf2(h0, h1);
    g_WM[row * 40 + (co & 31)] = packbf2(v0 - h0, v1 - h1);
}

// ---------------------------------------------------------------------------
// Implicit-GEMM conv3x3 SAME + bias + ReLU via bf16x2 (3-product) mma k16.
// 256 thr = 8 N-warps; CO tile 32 (2 m16/warp); 16 channels per K-slice.
// cp.async double-buffered; conflict-free strides (SLS,40 ≡ 8 mod 32).
// ---------------------------------------------------------------------------
template <int H, int W, int CI, int CO, int NB, int NROW, int SLS, bool OUT_SPLIT>
__global__ void __launch_bounds__(256, 2)
conv_bf16(const uint32_t* __restrict__ inH, const uint32_t* __restrict__ inM,
          const uint32_t* __restrict__ wH,  const uint32_t* __restrict__ wM,
          const float* __restrict__ bias, float* __restrict__ outF,
          __nv_bfloat16* __restrict__ outH, __nv_bfloat16* __restrict__ outM)
{
    constexpr int WP = W + 2, HP = H + 2;
    constexpr int SP2 = W + 2;
    constexpr int GP = HP * WP;                 // global plane (words)
    constexpr int PLANE = (NROW + 2) * SP2;     // staged plane (words)
    constexpr int BN = NB * NROW * W;
    constexpr int WN = BN / 8;
    constexpr int NC = WN / 8;
    constexpr int SIN = NB * 8 * SLS;           // u32 per input buffer (h or m)
    constexpr int SWW = 72 * 40;                // u32 per weight buffer
    constexpr int NCHI = PLANE / 4;
    constexpr int TCHI = NB * 8 * NCHI;
    constexpr int TCHW = SWW / 4;
    constexpr int NSLICE = CI / 16;

    extern __shared__ uint32_t smu[];
    uint32_t* sInH[2] = { smu,            smu + SIN };
    uint32_t* sInM[2] = { smu + 2 * SIN,  smu + 3 * SIN };
    uint32_t* sWH[2]  = { smu + 4 * SIN,  smu + 4 * SIN + SWW };
    uint32_t* sWM[2]  = { smu + 4 * SIN + 2 * SWW, smu + 4 * SIN + 3 * SWW };

    const int tid = threadIdx.x, warp = tid >> 5, lane = tid & 31;
    const int kk = lane & 3, ng = lane >> 2, wn = warp;
    const int ty0 = blockIdx.x * NROW;
    const int oc0 = blockIdx.y * 32;
    const int b0  = blockIdx.z * NB;

    int boff[NC];
#pragma unroll
    for (int ch = 0; ch < NC; ch++) {
        int n = wn * WN + ch * 8 + ng;
        int x = n % W; int t = n / W;
        int yy = t % NROW; int im = t / NROW;
        boff[ch] = (im * 8 + kk) * SLS + yy * SP2 + x;
    }

    float acc[2][NC][4];
#pragma unroll
    for (int mt = 0; mt < 2; mt++)
#pragma unroll
        for (int ch = 0; ch < NC; ch++)
#pragma unroll
            for (int j = 0; j < 4; j++) acc[mt][ch][j] = 0.f;

    auto stage = [&](int sl, int bufi) {
        uint32_t dH = (uint32_t)__cvta_generic_to_shared(sInH[bufi]);
        uint32_t dM = (uint32_t)__cvta_generic_to_shared(sInM[bufi]);
        for (int i = tid; i < TCHI; i += 256) {
            int c = i % NCHI; int t = i / NCHI;
            int pc = t % 8; int im = t / 8;
            size_t gbase = ((size_t)(b0 + im) * (CI / 2) + sl * 8 + pc) * GP
                         + (size_t)ty0 * WP + 4 * c;
            uint32_t soff = (uint32_t)(((im * 8 + pc) * SLS + 4 * c) * 4);
            cp16(dH + soff, inH + gbase);
            cp16(dM + soff, inM + gbase);
        }
        uint32_t dWH = (uint32_t)__cvta_generic_to_shared(sWH[bufi]);
        uint32_t dWM = (uint32_t)__cvta_generic_to_shared(sWM[bufi]);
        size_t wbase = ((size_t)blockIdx.y * (CI / 2) + sl * 8) * 9 * 40;
        for (int i = tid; i < TCHW; i += 256) {
            cp16(dWH + (uint32_t)(i * 16), wH + wbase + 4 * i);
            cp16(dWM + (uint32_t)(i * 16), wM + wbase + 4 * i);
        }
        asm volatile("cp.async.commit_group;" ::: "memory");
    };

    stage(0, 0);
    for (int s = 0; s < NSLICE; s++) {
        if (s + 1 < NSLICE) {
            stage(s + 1, (s + 1) & 1);
            asm volatile("cp.async.wait_group 1;" ::: "memory");
        } else {
            asm volatile("cp.async.wait_group 0;" ::: "memory");
        }
        __syncthreads();

        const uint32_t* siH = sInH[s & 1];
        const uint32_t* siM = sInM[s & 1];
        const uint32_t* swH = sWH[s & 1];
        const uint32_t* swM = sWM[s & 1];
#pragma unroll 1
        for (int kj = 0; kj < 9; kj++) {
            const int kyx = (kj / 3) * SP2 + (kj % 3);
            const int abase = kk * 9 * 40 + kj * 40 + ng;
            uint32_t ah[2][4], am[2][4];
#pragma unroll
            for (int mt = 0; mt < 2; mt++) {
                ah[mt][0] = swH[abase + mt * 16];
                ah[mt][1] = swH[abase + mt * 16 + 8];
                ah[mt][2] = swH[abase + 4 * 9 * 40 + mt * 16];
                ah[mt][3] = swH[abase + 4 * 9 * 40 + mt * 16 + 8];
                am[mt][0] = swM[abase + mt * 16];
                am[mt][1] = swM[abase + mt * 16 + 8];
                am[mt][2] = swM[abase + 4 * 9 * 40 + mt * 16];
                am[mt][3] = swM[abase + 4 * 9 * 40 + mt * 16 + 8];
            }
            uint32_t bh[NC][2], bm[NC][2];
#pragma unroll
            for (int ch = 0; ch < NC; ch++) {
                bh[ch][0] = siH[boff[ch] + kyx];
                bh[ch][1] = siH[boff[ch] + kyx + 4 * SLS];
                bm[ch][0] = siM[boff[ch] + kyx];
                bm[ch][1] = siM[boff[ch] + kyx + 4 * SLS];
            }
            // pass 1: h*h
#pragma unroll
            for (int ch = 0; ch < NC; ch++)
#pragma unroll
                for (int mt = 0; mt < 2; mt++)
                    mma_bf16(acc[mt][ch], ah[mt][0], ah[mt][1], ah[mt][2], ah[mt][3],
                             bh[ch][0], bh[ch][1]);
            // pass 2: h_w * m_x
#pragma unroll
            for (int ch = 0; ch < NC; ch++)
#pragma unroll
                for (int mt = 0; mt < 2; mt++)
                    mma_bf16(acc[mt][ch], ah[mt][0], ah[mt][1], ah[mt][2], ah[mt][3],
                             bm[ch][0], bm[ch][1]);
            // pass 3: m_w * h_x
#pragma unroll
            for (int ch = 0; ch < NC; ch++)
#pragma unroll
                for (int mt = 0; mt < 2; mt++)
                    mma_bf16(acc[mt][ch], am[mt][0], am[mt][1], am[mt][2], am[mt][3],
                             bh[ch][0], bh[ch][1]);
        }
        __syncthreads();
    }

    // epilogue
#pragma unroll
    for (int mt = 0; mt < 2; mt++) {
        const int co = oc0 + mt * 16 + ng;
        const float bva = bias[co];
        const float bvb = bias[co + 8];
#pragma unroll
        for (int ch = 0; ch < NC; ch++) {
#pragma unroll
            for (int j = 0; j < 2; j++) {
                int n = wn * WN + ch * 8 + kk * 2 + j;
                int x = n % W; int t = n / W;
                int yy = t % NROW; int im = t / NROW;
                float v0 = fmaxf(acc[mt][ch][j] + bva, 0.f);
                float v1 = fmaxf(acc[mt][ch][j + 2] + bvb, 0.f);
                if constexpr (OUT_SPLIT) {
                    size_t w0 = ((size_t)(b0 + im) * (CO / 2) + (co >> 1)) * GP
                              + (size_t)(ty0 + yy + 1) * WP + (x + 1);
                    size_t i0 = w0 * 2 + (co & 1);
                    __nv_bfloat16 hb0 = __float2bfloat16(v0);
                    outH[i0] = hb0;
                    outM[i0] = __float2bfloat16(v0 - __bfloat162float(hb0));
                    int co1 = co + 8;
                    size_t w1 = ((size_t)(b0 + im) * (CO / 2) + (co1 >> 1)) * GP
                              + (size_t)(ty0 + yy + 1) * WP + (x + 1);
                    size_t i1 = w1 * 2 + (co1 & 1);
                    __nv_bfloat16 hb1 = __float2bfloat16(v1);
                    outH[i1] = hb1;
                    outM[i1] = __float2bfloat16(v1 - __bfloat162float(hb1));
                } else {
                    size_t base = (((size_t)(b0 + im) * CO + co) * H + (ty0 + yy)) * W + x;
                    outF[base] = v0;
                    outF[base + (size_t)8 * H * W] = v1;
                }
            }
        }
    }
}

// ---------------------------------------------------------------------------
// conv0: direct fp32 3->64 @64x64, fused pool, writes packed S1 h/m.
// ---------------------------------------------------------------------------
__global__ void __launch_bounds__(256)
conv0_k(const float* __restrict__ in, const float* __restrict__ wt,
        const float* __restrict__ bias, uint32_t* __restrict__ outHp,
        uint32_t* __restrict__ outMp)
{
    constexpr int H = 64, W = 64, CI = 3, CO = 64;
    constexpr int TPH = 16, TPW = 16, RPH = 4, RPW = 4, OCT = 64, RC = 4;
    constexpr int NPXW = TPW / RPW;
    constexpr int NPX  = (TPH / RPH) * NPXW;
    constexpr int SP   = TPW + 4;

    __shared__ __align__(16) float s_in[CI * (TPH + 2) * SP];
    __shared__ __align__(16) float s_w[CI * OCT * 12];

    const int tiles_w = W / TPW;
    const int ty0 = (blockIdx.x / tiles_w) * TPH;
    const int tx0 = (blockIdx.x % tiles_w) * TPW;
    const int b   = blockIdx.z;

    const int tid = threadIdx.x;
    const int pix = tid % NPX;
    const int ch  = tid / NPX;
    const int ly  = (pix / NPXW) * RPH;
    const int lx  = (pix % NPXW) * RPW;
    const int oc  = ch * RC;

    float acc[RC][RPH][RPW];
#pragma unroll
    for (int c = 0; c < RC; c++)
#pragma unroll
        for (int yy = 0; yy < RPH; yy++)
#pragma unroll
            for (int xx = 0; xx < RPW; xx++) acc[c][yy][xx] = 0.f;

    {
        constexpr int INEL = CI * (TPH + 2) * (TPW + 2);
        for (int idx = tid; idx < INEL; idx += 256) {
            int t = idx;
            const int ix = t % (TPW + 2); t /= (TPW + 2);
            const int iy = t % (TPH + 2); t /= (TPH + 2);
            const int ic = t;
            const int gy = ty0 + iy - 1, gx = tx0 + ix - 1;
            float v = 0.f;
            if (gy >= 0 && gy < H && gx >= 0 && gx < W)
                v = in[(((size_t)b * CI + ic) * H + gy) * W + gx];
            s_in[(ic * (TPH + 2) + iy) * SP + ix] = v;
        }
        for (int idx = tid; idx < CI * OCT * 9; idx += 256) {
            int t = idx;
            const int tt = t % 9;  t /= 9;
            const int ic = t % CI; t /= CI;
            const int o  = t;
            s_w[(ic * OCT + o) * 12 + tt] = wt[((size_t)o * CI + ic) * 9 + tt];
        }
        __syncthreads();

#pragma unroll
        for (int ic = 0; ic < CI; ic++) {
            const float* sbase = &s_in[(ic * (TPH + 2)) * SP];
            float wv[RC][9];
#pragma unroll
            for (int c = 0; c < RC; c++) {
                const float4* wp = (const float4*)&s_w[(ic * OCT + ch * RC + c) * 12];
                float4 w0 = wp[0], w1 = wp[1], w2 = wp[2];
                wv[c][0] = w0.x; wv[c][1] = w0.y; wv[c][2] = w0.z;
                wv[c][3] = w0.w; wv[c][4] = w1.x; wv[c][5] = w1.y;
                wv[c][6] = w1.z; wv[c][7] = w1.w; wv[c][8] = w2.x;
            }
            float r[3][8];
            {
                float4 u = *(const float4*)(sbase + (ly + 0) * SP + lx);
                float4 v = *(const float4*)(sbase + (ly + 0) * SP + lx + 4);
                r[0][0]=u.x;r[0][1]=u.y;r[0][2]=u.z;r[0][3]=u.w;r[0][4]=v.x;r[0][5]=v.y;r[0][6]=v.z;r[0][7]=v.w;
                u = *(const float4*)(sbase + (ly + 1) * SP + lx);
                v = *(const float4*)(sbase + (ly + 1) * SP + lx + 4);
                r[1][0]=u.x;r[1][1]=u.y;r[1][2]=u.z;r[1][3]=u.w;r[1][4]=v.x;r[1][5]=v.y;r[1][6]=v.z;r[1][7]=v.w;
            }
#pragma unroll
            for (int yy = 0; yy < RPH; yy++) {
                {
                    int rr = (yy + 2) % 3;
                    float4 u = *(const float4*)(sbase + (ly + yy + 2) * SP + lx);
                    float4 v = *(const float4*)(sbase + (ly + yy + 2) * SP + lx + 4);
                    r[rr][0]=u.x;r[rr][1]=u.y;r[rr][2]=u.z;r[rr][3]=u.w;r[rr][4]=v.x;r[rr][5]=v.y;r[rr][6]=v.z;r[rr][7]=v.w;
                }
                const int i0 = yy % 3, i1 = (yy + 1) % 3, i2 = (yy + 2) % 3;
#pragma unroll
                for (int c = 0; c < RC; c++)
#pragma unroll
                    for (int xx = 0; xx < RPW; xx++) {
                        float a = acc[c][yy][xx];
                        a = fmaf(wv[c][0], r[i0][xx],     a);
                        a = fmaf(wv[c][1], r[i0][xx + 1], a);
                        a = fmaf(wv[c][2], r[i0][xx + 2], a);
                        a = fmaf(wv[c][3], r[i1][xx],     a);
                        a = fmaf(wv[c][4], r[i1][xx + 1], a);
                        a = fmaf(wv[c][5], r[i1][xx + 2], a);
                        a = fmaf(wv[c][6], r[i2][xx],     a);
                        a = fmaf(wv[c][7], r[i2][xx + 1], a);
                        a = fmaf(wv[c][8], r[i2][xx + 2], a);
                        acc[c][yy][xx] = a;
                    }
            }
        }
    }

    // pool + bias + relu + packed split store [64][32][34*34]
#pragma unroll
    for (int p = 0; p < RC / 2; p++) {
        const float bv0 = bias[oc + 2 * p];
        const float bv1 = bias[oc + 2 * p + 1];
#pragma unroll
        for (int y2 = 0; y2 < RPH / 2; y2++)
#pragma unroll
            for (int x2 = 0; x2 < RPW / 2; x2++) {
                int c0 = 2 * p, c1 = 2 * p + 1;
                float a0 = fmaxf(fmaxf(acc[c0][2*y2][2*x2], acc[c0][2*y2][2*x2+1]),
                                 fmaxf(acc[c0][2*y2+1][2*x2], acc[c0][2*y2+1][2*x2+1]));
                float a1 = fmaxf(fmaxf(acc[c1][2*y2][2*x2], acc[c1][2*y2][2*x2+1]),
                                 fmaxf(acc[c1][2*y2+1][2*x2], acc[c1][2*y2+1][2*x2+1]));
                float v0 = fmaxf(a0 + bv0, 0.f);
                float v1 = fmaxf(a1 + bv1, 0.f);
                float h0 = __bfloat162float(__float2bfloat16(v0));
                float h1 = __bfloat162float(__float2bfloat16(v1));
                int py = (ty0 + ly) / 2 + y2, px = (tx0 + lx) / 2 + x2;
                size_t w = ((size_t)b * 32 + (oc >> 1) + p) * (34 * 34)
                         + (size_t)(py + 1) * 34 + (px + 1);
                outHp[w] = packbf2(h0, h1);
                outMp[w] = packbf2(v0 - h0, v1 - h1);
            }
    }
}

// ---------------------------------------------------------------------------
// 2x2 maxpool fp32 NCHW -> packed split padded pair tensor
// ---------------------------------------------------------------------------
__global__ void pool_split_p(const float* __restrict__ in, uint32_t* __restrict__ outh,
                             uint32_t* __restrict__ outm, int total, int C, int H, int W)
{
    int i = blockIdx.x * blockDim.x + threadIdx.x;
    if (i >= total) return;                      // total = B*(C/2)*HO*WO
    int WO = W >> 1, HO = H >> 1;
    int x = i % WO;
    int t = i / WO;
    int y = t % HO; t /= HO;
    int pc = t % (C / 2);
    int b = t / (C / 2);
    const float* p0 = in + ((size_t)(b * C + 2 * pc) * H + 2 * y) * W + 2 * x;
    const float* p1 = p0 + (size_t)H * W;
    float v0 = fmaxf(fmaxf(p0[0], p0[1]), fmaxf(p0[W], p0[W + 1]));
    float v1 = fmaxf(fmaxf(p1[0], p1[1]), fmaxf(p1[W], p1[W + 1]));
    float h0 = __bfloat162float(__float2bfloat16(v0));
    float h1 = __bfloat162float(__float2bfloat16(v1));
    size_t w = ((size_t)(b * (C / 2) + pc)) * (size_t)((HO + 2) * (WO + 2))
             + (size_t)(y + 1) * (WO + 2) + (x + 1);
    outh[w] = packbf2(h0, h1);
    outm[w] = packbf2(v0 - h0, v1 - h1);
}

// ---------------------------------------------------------------------------
// Engram mask + final 2x2 pool + flatten to [B, 2048].
// ---------------------------------------------------------------------------
__global__ void mask_pool_flatten(const float* __restrict__ h,
                                  const int* __restrict__ y,
                                  const int* __restrict__ b_table,
                                  float* __restrict__ out)
{
    int b = blockIdx.x;
    __shared__ int ids[128];
    int t = threadIdx.x;
    if (t < 128) ids[t] = b_table[y[b] * 128 + t];
    __syncthreads();
    int c = t;
    bool on = false;
#pragma unroll 16
    for (int j = 0; j < 128; j++) on |= (ids[j] == c);
    float m = on ? 1.f : 0.f;
    const float* p = h + ((size_t)(b * 512 + c) * 16);
#pragma unroll
    for (int py = 0; py < 2; py++)
#pragma unroll
        for (int px = 0; px < 2; px++) {
            const float* q = p + (2 * py) * 4 + 2 * px;
            float v = fmaxf(fmaxf(q[0], q[1]), fmaxf(q[4], q[5]));
            out[(size_t)b * 2048 + c * 4 + py * 2 + px] = v * m;
        }
}

// ---------------------------------------------------------------------------
// FC layers (fp32).
// ---------------------------------------------------------------------------
template <bool RELU>
__global__ void __launch_bounds__(256)
fc_v2(const float* __restrict__ A, const float* __restrict__ W,
      const float* __restrict__ bias, float* __restrict__ C,
      int N, int K, int Klen)
{
    __shared__ __align__(16) float sA[16 * 68];
    __shared__ __align__(16) float sB[16 * 34];
    const int n0 = blockIdx.x * 32;
    const int k0base = blockIdx.y * Klen;
    float* Cp = C + (size_t)blockIdx.y * 64 * N;
    const int tid = threadIdx.x;
    const int tm = (tid / 16) * 4;
    const int tn = (tid % 16) * 2;
    float acc[4][2] = {};

    for (int k0 = k0base; k0 < k0base + Klen; k0 += 16) {
        __syncthreads();
        for (int i = tid; i < 64 * 16; i += 256) {
            int r = i / 16, kk = i % 16;
            sA[kk * 68 + r] = A[(size_t)r * K + k0 + kk];
        }
        for (int i = tid; i < 32 * 16; i += 256) {
            int cidx = i / 16, kk = i % 16;
            int col = n0 + cidx;
            sB[kk * 34 + cidx] = (col < N) ? W[(size_t)col * K + k0 + kk] : 0.f;
        }
        __syncthreads();
#pragma unroll
        for (int kk = 0; kk < 16; kk++) {
            float4 a = *(const float4*)&sA[kk * 68 + tm];
            float2 b = *(const float2*)&sB[kk * 34 + tn];
            acc[0][0] = fmaf(a.x, b.x, acc[0][0]);
            acc[0][1] = fmaf(a.x, b.y, acc[0][1]);
            acc[1][0] = fmaf(a.y, b.x, acc[1][0]);
            acc[1][1] = fmaf(a.y, b.y, acc[1][1]);
            acc[2][0] = fmaf(a.z, b.x, acc[2][0]);
            acc[2][1] = fmaf(a.z, b.y, acc[2][1]);
            acc[3][0] = fmaf(a.w, b.x, acc[3][0]);
            acc[3][1] = fmaf(a.w, b.y, acc[3][1]);
        }
    }
#pragma unroll
    for (int j = 0; j < 2; j++) {
        int col = n0 + tn + j;
        if (col >= N) continue;
        float bv = bias ? bias[col] : 0.f;
#pragma unroll
        for (int i = 0; i < 4; i++) {
            float v = acc[i][j] + bv;
            if (RELU) v = fmaxf(v, 0.f);
            Cp[(size_t)(tm + i) * N + col] = v;
        }
    }
}

__global__ void fc3_combine(const float* __restrict__ part,
                            const float* __restrict__ bias,
                            float* __restrict__ out, int N, int total)
{
    int i = blockIdx.x * blockDim.x + threadIdx.x;
    if (i >= total) return;
    int n = i % N;
    out[i] = part[i] + part[64 * N + i] + part[2 * 64 * N + i]
           + part[3 * 64 * N + i] + bias[n];
}

// ---------------------------------------------------------------------------
// Launch
// ---------------------------------------------------------------------------
extern "C" void kernel_launch(void* const* d_in, const int* in_sizes, int n_in,
                              void* d_out, int out_size)
{
    const float* x    = (const float*)d_in[0];
    const int*   y    = (const int*)d_in[1];
    const int*   bt   = (const int*)d_in[2];
    const float* cw0  = (const float*)d_in[3];
    const float* cb0  = (const float*)d_in[4];
    const float* cw1  = (const float*)d_in[5];
    const float* cb1  = (const float*)d_in[6];
    const float* cw2a = (const float*)d_in[7];
    const float* cb2a = (const float*)d_in[8];
    const float* cw2b = (const float*)d_in[9];
    const float* cb2b = (const float*)d_in[10];
    const float* cw3a = (const float*)d_in[11];
    const float* cb3a = (const float*)d_in[12];
    const float* cw3b = (const float*)d_in[13];
    const float* cb3b = (const float*)d_in[14];
    const float* cw4a = (const float*)d_in[15];
    const float* cb4a = (const float*)d_in[16];
    const float* cw4b = (const float*)d_in[17];
    const float* cb4b = (const float*)d_in[18];
    const float* fw1  = (const float*)d_in[19];
    const float* fb1  = (const float*)d_in[20];
    const float* fw2  = (const float*)d_in[21];
    const float* fb2  = (const float*)d_in[22];
    const float* fw3  = (const float*)d_in[23];
    const float* fb3  = (const float*)d_in[24];

    float* A;  float* Bp;
    uint32_t *S1h,*S1m,*S2h,*S2m,*S3h,*S3m,*S4h,*S4m,*S5h,*S5m,*S6h,*S6m,*S7h,*S7m;
    uint32_t *WH, *WM;
    cudaGetSymbolAddress((void**)&A, g_A);
    cudaGetSymbolAddress((void**)&Bp, g_B);
    cudaGetSymbolAddress((void**)&S1h, gS1h); cudaGetSymbolAddress((void**)&S1m, gS1m);
    cudaGetSymbolAddress((void**)&S2h, gS2h); cudaGetSymbolAddress((void**)&S2m, gS2m);
    cudaGetSymbolAddress((void**)&S3h, gS3h); cudaGetSymbolAddress((void**)&S3m, gS3m);
    cudaGetSymbolAddress((void**)&S4h, gS4h); cudaGetSymbolAddress((void**)&S4m, gS4m);
    cudaGetSymbolAddress((void**)&S5h, gS5h); cudaGetSymbolAddress((void**)&S5m, gS5m);
    cudaGetSymbolAddress((void**)&S6h, gS6h); cudaGetSymbolAddress((void**)&S6m, gS6m);
    cudaGetSymbolAddress((void**)&S7h, gS7h); cudaGetSymbolAddress((void**)&S7m, gS7m);
    cudaGetSymbolAddress((void**)&WH, g_WH);  cudaGetSymbolAddress((void**)&WM, g_WM);

    prep_w_all<<<(4608000 + 255) / 256, 256>>>(cw1, cw2a, cw2b, cw3a, cw3b, cw4a, cw4b);
    conv0_k<<<dim3(16, 1, 64), 256>>>(x, cw0, cb0, S1h, S1m);

    // conv1 64->128 @32x32 -> Bp fp32; pool -> S2
    {
        auto k = conv_bf16<32, 32, 64, 128, 1, 8, 360, false>;
        constexpr int SIN = 8 * 360;
        size_t sm = (size_t)(4 * SIN + 4 * 2880) * 4;
        cudaFuncSetAttribute(k, cudaFuncAttributeMaxDynamicSharedMemorySize, (int)sm);
        k<<<dim3(4, 4, 64), 256, sm>>>(S1h, S1m, WH + (size_t)ROFF_C1 * 40,
                                       WM + (size_t)ROFF_C1 * 40, cb1, Bp, nullptr, nullptr);
        int total = 64 * 64 * 16 * 16;
        pool_split_p<<<(total + 255)/256, 256>>>(Bp, S2h, S2m, total, 128, 32, 32);
    }
    // conv2a 128->256 @16x16 -> S3 split
    {
        auto k = conv_bf16<16, 16, 128, 256, 1, 16, 328, true>;
        constexpr int SIN = 8 * 328;
        size_t sm = (size_t)(4 * SIN + 4 * 2880) * 4;
        cudaFuncSetAttribute(k, cudaFuncAttributeMaxDynamicSharedMemorySize, (int)sm);
        k<<<dim3(1, 8, 64), 256, sm>>>(S2h, S2m, WH + (size_t)ROFF_C2A * 40,
                                       WM + (size_t)ROFF_C2A * 40, cb2a, nullptr,
                                       (__nv_bfloat16*)S3h, (__nv_bfloat16*)S3m);
    }
    // conv2b 256->256 @16x16 -> Bp fp32; pool -> S4
    {
        auto k = conv_bf16<16, 16, 256, 256, 1, 16, 328, false>;
        constexpr int SIN = 8 * 328;
        size_t sm = (size_t)(4 * SIN + 4 * 2880) * 4;
        cudaFuncSetAttribute(k, cudaFuncAttributeMaxDynamicSharedMemorySize, (int)sm);
        k<<<dim3(1, 8, 64), 256, sm>>>(S3h, S3m, WH + (size_t)ROFF_C2B * 40,
                                       WM + (size_t)ROFF_C2B * 40, cb2b, Bp, nullptr, nullptr);
        int total = 64 * 128 * 8 * 8;
        pool_split_p<<<(total + 255)/256, 256>>>(Bp, S4h, S4m, total, 256, 16, 16);
    }
    // conv3a 256->512 @8x8 (NB=2) -> S5 split
    {
        auto k = conv_bf16<8, 8, 256, 512, 2, 8, 104, true>;
        constexpr int SIN = 2 * 8 * 104;
        size_t sm = (size_t)(4 * SIN + 4 * 2880) * 4;
        cudaFuncSetAttribute(k, cudaFuncAttributeMaxDynamicSharedMemorySize, (int)sm);
        k<<<dim3(1, 16, 32), 256, sm>>>(S4h, S4m, WH + (size_t)ROFF_C3A * 40,
                                        WM + (size_t)ROFF_C3A * 40, cb3a, nullptr,
                                        (__nv_bfloat16*)S5h, (__nv_bfloat16*)S5m);
    }
    // conv3b 512->512 @8x8 -> Bp fp32; pool -> S6
    {
        auto k = conv_bf16<8, 8, 512, 512, 2, 8, 104, false>;
        constexpr int SIN = 2 * 8 * 104;
        size_t sm = (size_t)(4 * SIN + 4 * 2880) * 4;
        cudaFuncSetAttribute(k, cudaFuncAttributeMaxDynamicSharedMemorySize, (int)sm);
        k<<<dim3(1, 16, 32), 256, sm>>>(S5h, S5m, WH + (size_t)ROFF_C3B * 40,
                                        WM + (size_t)ROFF_C3B * 40, cb3b, Bp, nullptr, nullptr);
        int total = 64 * 256 * 4 * 4;
        pool_split_p<<<(total + 255)/256, 256>>>(Bp, S6h, S6m, total, 512, 8, 8);
    }
    // conv4a 512->512 @4x4 (NB=4) -> S7 split
    {
        auto k = conv_bf16<4, 4, 512, 512, 4, 4, 40, true>;
        constexpr int SIN = 4 * 8 * 40;
        size_t sm = (size_t)(4 * SIN + 4 * 2880) * 4;
        cudaFuncSetAttribute(k, cudaFuncAttributeMaxDynamicSharedMemorySize, (int)sm);
        k<<<dim3(1, 16, 16), 256, sm>>>(S6h, S6m, WH + (size_t)ROFF_C4A * 40,
                                        WM + (size_t)ROFF_C4A * 40, cb4a, nullptr,
                                        (__nv_bfloat16*)S7h, (__nv_bfloat16*)S7m);
    }
    // conv4b 512->512 @4x4 -> Bp fp32
    {
        auto k = conv_bf16<4, 4, 512, 512, 4, 4, 40, false>;
        constexpr int SIN = 4 * 8 * 40;
        size_t sm = (size_t)(4 * SIN + 4 * 2880) * 4;
        cudaFuncSetAttribute(k, cudaFuncAttributeMaxDynamicSharedMemorySize, (int)sm);
        k<<<dim3(1, 16, 16), 256, sm>>>(S7h, S7m, WH + (size_t)ROFF_C4B * 40,
                                        WM + (size_t)ROFF_C4B * 40, cb4b, Bp, nullptr, nullptr);
    }

    // engram mask + pool -> flatten [64, 2048] -> A
    mask_pool_flatten<<<64, 512>>>(Bp, y, bt, A);

    // classifier
    fc_v2<true><<<dim3(128, 1), 256>>>(A, fw1, fb1, Bp, 4096, 2048, 2048);
    fc_v2<true><<<dim3(128, 1), 256>>>(Bp, fw2, fb2, A, 4096, 4096, 4096);
    fc_v2<false><<<dim3(32, 4), 256>>>(A, fw3, nullptr, Bp, 1000, 4096, 1024);
    fc3_combine<<<(64000 + 255)/256, 256>>>(Bp, fb3, (float*)d_out, 1000, 64000);
}